// round 4
// baseline (speedup 1.0000x reference)
#include <cuda_runtime.h>
#include <cstdint>

#define NMAX   100000
#define EMAX   1600000
#define CDIM   50
#define HIDD   256
#define INDIM  500
#define KHOP   10

// ---------------- static scratch (no allocations allowed) ----------------
static __device__ float    g_x1[(size_t)NMAX * HIDD];
static __device__ float    g_H [(size_t)(KHOP + 1) * NMAX * CDIM];
static __device__ float    g_norm[NMAX];
static __device__ int      g_deg   [NMAX];
static __device__ int      g_rowptr[NMAX + 1];
static __device__ int      g_cursor[NMAX];
static __device__ int      g_bsum  [1024];
static __device__ int      g_col   [EMAX];
static __device__ uint32_t g_w1h[INDIM * HIDD];
static __device__ uint32_t g_w1l[INDIM * HIDD];
static __device__ uint32_t g_w2h[HIDD * CDIM];
static __device__ uint32_t g_w2l[HIDD * CDIM];

// ================= TF32 helpers =================
__device__ __forceinline__ void f2tf32(float x, uint32_t& hi, uint32_t& lo) {
    asm("cvt.rna.tf32.f32 %0, %1;" : "=r"(hi) : "f"(x));
    float r = x - __uint_as_float(hi);
    asm("cvt.rna.tf32.f32 %0, %1;" : "=r"(lo) : "f"(r));
}

__device__ __forceinline__ void mma_tf32(float* c, const uint32_t* a, const uint32_t* b) {
    asm volatile(
        "mma.sync.aligned.m16n8k8.row.col.f32.tf32.tf32.f32 "
        "{%0,%1,%2,%3}, {%4,%5,%6,%7}, {%8,%9}, {%0,%1,%2,%3};"
        : "+f"(c[0]), "+f"(c[1]), "+f"(c[2]), "+f"(c[3])
        : "r"(a[0]), "r"(a[1]), "r"(a[2]), "r"(a[3]), "r"(b[0]), "r"(b[1]));
}

// decompose fp32 weights -> tf32 hi/lo planes (done once, tiny)
__global__ void decomp_kernel(const float* __restrict__ W,
                              uint32_t* __restrict__ Wh, uint32_t* __restrict__ Wl, int n) {
    int i = blockIdx.x * blockDim.x + threadIdx.x;
    if (i < n) { uint32_t h, l; f2tf32(W[i], h, l); Wh[i] = h; Wl[i] = l; }
}

// ================= templated 3xTF32 GEMM =================
// C = op(A @ B + bias). A:[M,K] fp32 row, B pre-decomposed u32 hi/lo [K,N] row.
// Block tile 128 x TBN x 16, 256 threads = 8 warps (2 x 4), warp tile 64 x (TBN/4).
#define TBM 128
#define TBK 16
#define TPAD 8

template <int TBN, bool RELU>
__global__ __launch_bounds__(256)
void gemm_tf32(const float* __restrict__ A,
               const uint32_t* __restrict__ Bhg, const uint32_t* __restrict__ Blg,
               const float* __restrict__ bias, float* __restrict__ C,
               int M, int N, int K) {
    constexpr int NI = TBN / 32;                 // mma n-tiles per warp
    __shared__ uint32_t Ah[TBK][TBM + TPAD];
    __shared__ uint32_t Al[TBK][TBM + TPAD];
    __shared__ uint32_t Bh[TBK][TBN + TPAD];
    __shared__ uint32_t Bl[TBK][TBN + TPAD];

    const int tid  = threadIdx.x;
    const int lane = tid & 31;
    const int wid  = tid >> 5;
    const int wm   = (wid & 1) * 64;
    const int wn   = (wid >> 1) * (TBN / 4);
    const int g    = lane >> 2;
    const int tg   = lane & 3;
    const int row0 = blockIdx.y * TBM;
    const int col0 = blockIdx.x * TBN;

    float acc[4][NI][4];
#pragma unroll
    for (int i = 0; i < 4; i++)
#pragma unroll
        for (int j = 0; j < NI; j++)
#pragma unroll
            for (int q = 0; q < 4; q++) acc[i][j][q] = 0.f;

    const bool full_m = (row0 + TBM <= M);
    const bool full_n = (col0 + TBN <= N);

    for (int kt = 0; kt < K; kt += TBK) {
        const bool full_k = (kt + TBK <= K);
        // ---- A tile ----
        if (full_m && full_k) {
#pragma unroll
            for (int it = tid; it < TBM * 4; it += 256) {
                int r = it >> 2, c4 = (it & 3) * 4;
                float4 v = *reinterpret_cast<const float4*>(A + (size_t)(row0 + r) * K + kt + c4);
                uint32_t h, l;
                f2tf32(v.x, h, l); Ah[c4 + 0][r] = h; Al[c4 + 0][r] = l;
                f2tf32(v.y, h, l); Ah[c4 + 1][r] = h; Al[c4 + 1][r] = l;
                f2tf32(v.z, h, l); Ah[c4 + 2][r] = h; Al[c4 + 2][r] = l;
                f2tf32(v.w, h, l); Ah[c4 + 3][r] = h; Al[c4 + 3][r] = l;
            }
        } else {
            for (int it = tid; it < TBM * TBK; it += 256) {
                int r = it / TBK, c = it % TBK;
                int gr = row0 + r, gk = kt + c;
                float x = (gr < M && gk < K) ? A[(size_t)gr * K + gk] : 0.f;
                uint32_t h, l; f2tf32(x, h, l);
                Ah[c][r] = h; Al[c][r] = l;
            }
        }
        // ---- B tile (pre-decomposed) ----
        if (full_n && full_k) {
#pragma unroll
            for (int it = tid; it < TBK * (TBN / 4); it += 256) {
                int r = it / (TBN / 4), c4 = (it % (TBN / 4)) * 4;
                size_t off = (size_t)(kt + r) * N + col0 + c4;
                uint4 vh = *reinterpret_cast<const uint4*>(Bhg + off);
                uint4 vl = *reinterpret_cast<const uint4*>(Blg + off);
                Bh[r][c4 + 0] = vh.x; Bh[r][c4 + 1] = vh.y; Bh[r][c4 + 2] = vh.z; Bh[r][c4 + 3] = vh.w;
                Bl[r][c4 + 0] = vl.x; Bl[r][c4 + 1] = vl.y; Bl[r][c4 + 2] = vl.z; Bl[r][c4 + 3] = vl.w;
            }
        } else {
            for (int it = tid; it < TBK * TBN; it += 256) {
                int r = it / TBN, c = it % TBN;
                int gk = kt + r, gc = col0 + c;
                bool ok = (gk < K && gc < N);
                size_t off = (size_t)gk * N + gc;
                Bh[r][c] = ok ? Bhg[off] : 0u;
                Bl[r][c] = ok ? Blg[off] : 0u;
            }
        }
        __syncthreads();

#pragma unroll
        for (int ks = 0; ks < 2; ks++) {
            const int k0 = ks * 8;
            uint32_t ah[4][4], al[4][4], bh[NI][2], bl[NI][2];
#pragma unroll
            for (int mi = 0; mi < 4; mi++) {
                int m = wm + mi * 16;
                ah[mi][0] = Ah[k0 + tg    ][m + g    ];
                ah[mi][1] = Ah[k0 + tg    ][m + g + 8];
                ah[mi][2] = Ah[k0 + 4 + tg][m + g    ];
                ah[mi][3] = Ah[k0 + 4 + tg][m + g + 8];
                al[mi][0] = Al[k0 + tg    ][m + g    ];
                al[mi][1] = Al[k0 + tg    ][m + g + 8];
                al[mi][2] = Al[k0 + 4 + tg][m + g    ];
                al[mi][3] = Al[k0 + 4 + tg][m + g + 8];
            }
#pragma unroll
            for (int ni = 0; ni < NI; ni++) {
                int n = wn + ni * 8;
                bh[ni][0] = Bh[k0 + tg    ][n + g];
                bh[ni][1] = Bh[k0 + 4 + tg][n + g];
                bl[ni][0] = Bl[k0 + tg    ][n + g];
                bl[ni][1] = Bl[k0 + 4 + tg][n + g];
            }
#pragma unroll
            for (int mi = 0; mi < 4; mi++)
#pragma unroll
                for (int ni = 0; ni < NI; ni++) {
                    mma_tf32(acc[mi][ni], ah[mi], bh[ni]);
                    mma_tf32(acc[mi][ni], al[mi], bh[ni]);
                    mma_tf32(acc[mi][ni], ah[mi], bl[ni]);
                }
        }
        __syncthreads();
    }

    // ---- epilogue ----
#pragma unroll
    for (int mi = 0; mi < 4; mi++) {
#pragma unroll
        for (int ni = 0; ni < NI; ni++) {
            int c = col0 + wn + ni * 8 + 2 * tg;
            float bv0 = (c < N) ? bias[c] : 0.f;
            float bv1 = (c + 1 < N) ? bias[c + 1] : 0.f;
            int r0 = row0 + wm + mi * 16 + g;
            int r1 = r0 + 8;
            if (r0 < M) {
                float v0 = acc[mi][ni][0] + bv0;
                float v1 = acc[mi][ni][1] + bv1;
                if (RELU) { v0 = fmaxf(v0, 0.f); v1 = fmaxf(v1, 0.f); }
                if (c + 1 < N)
                    *reinterpret_cast<float2*>(C + (size_t)r0 * N + c) = make_float2(v0, v1);
                else if (c < N)
                    C[(size_t)r0 * N + c] = v0;
            }
            if (r1 < M) {
                float v2 = acc[mi][ni][2] + bv0;
                float v3 = acc[mi][ni][3] + bv1;
                if (RELU) { v2 = fmaxf(v2, 0.f); v3 = fmaxf(v3, 0.f); }
                if (c + 1 < N)
                    *reinterpret_cast<float2*>(C + (size_t)r1 * N + c) = make_float2(v2, v3);
                else if (c < N)
                    C[(size_t)r1 * N + c] = v2;
            }
        }
    }
}

// ---------------- CSR build helpers ----------------
__global__ void zero_i_kernel(int* __restrict__ p, int n) {
    int i = blockIdx.x * blockDim.x + threadIdx.x;
    if (i < n) p[i] = 0;
}

__global__ void hist_kernel(const int* __restrict__ dst, int* __restrict__ deg, int E) {
    int i = blockIdx.x * blockDim.x + threadIdx.x;
    if (i < E) atomicAdd(&deg[dst[i]], 1);
}

__global__ void norm_kernel(const int* __restrict__ deg, float* __restrict__ nrm, int n) {
    int i = blockIdx.x * blockDim.x + threadIdx.x;
    if (i < n) nrm[i] = rsqrtf((float)deg[i]);
}

__global__ void scan_block(const int* __restrict__ deg, int* __restrict__ rowptr,
                           int* __restrict__ bsum, int n) {
    __shared__ int sh[512];
    int tid = threadIdx.x;
    int gid = blockIdx.x * 512 + tid;
    int v = (gid < n) ? deg[gid] : 0;
    sh[tid] = v;
    __syncthreads();
    for (int off = 1; off < 512; off <<= 1) {
        int t = (tid >= off) ? sh[tid - off] : 0;
        __syncthreads();
        sh[tid] += t;
        __syncthreads();
    }
    if (gid < n) rowptr[gid] = sh[tid] - v;
    if (tid == 511) bsum[blockIdx.x] = sh[511];
}

__global__ void scan_sums(int* __restrict__ bsum, int nb) {
    __shared__ int sh[1024];
    int tid = threadIdx.x;
    int v = (tid < nb) ? bsum[tid] : 0;
    sh[tid] = v;
    __syncthreads();
    for (int off = 1; off < 1024; off <<= 1) {
        int t = (tid >= off) ? sh[tid - off] : 0;
        __syncthreads();
        sh[tid] += t;
        __syncthreads();
    }
    if (tid < nb) bsum[tid] = sh[tid] - v;
}

__global__ void scan_finish(int* __restrict__ rowptr, const int* __restrict__ bsum,
                            int* __restrict__ cursor, int n, int E) {
    int gid = blockIdx.x * blockDim.x + threadIdx.x;
    if (gid < n) {
        int r = rowptr[gid] + bsum[gid / 512];
        rowptr[gid] = r;
        cursor[gid] = r;
    }
    if (gid == 0) rowptr[n] = E;
}

__global__ void fill_kernel(const int* __restrict__ src, const int* __restrict__ dst,
                            int* __restrict__ cursor, int* __restrict__ col, int E) {
    int e = blockIdx.x * blockDim.x + threadIdx.x;
    if (e >= E) return;
    int pos = atomicAdd(&cursor[dst[e]], 1);
    col[pos] = src[e];
}

// ---------------- fused pull-gather hop (float2 lanes) ----------------
// warp per node, lanes 0..24 each own a float2 column pair.
__global__ void spmm_pull(const int* __restrict__ rowptr, const int* __restrict__ col,
                          const float* __restrict__ nrm,
                          const float* __restrict__ hin, float* __restrict__ hout,
                          int N) {
    int t = blockIdx.x * blockDim.x + threadIdx.x;
    int n = t >> 5;
    int lane = t & 31;
    if (n >= N) return;

    int beg = rowptr[n];
    int end = rowptr[n + 1];
    const bool act = (lane < CDIM / 2);
    const int  c2  = lane * 2;

    float ax = 0.f, ay = 0.f;
    int j = beg;
    for (; j + 1 < end; j += 2) {
        int s0 = col[j], s1 = col[j + 1];
        float n0 = nrm[s0], n1 = nrm[s1];
        if (act) {
            float2 v0 = *reinterpret_cast<const float2*>(hin + (size_t)s0 * CDIM + c2);
            float2 v1 = *reinterpret_cast<const float2*>(hin + (size_t)s1 * CDIM + c2);
            ax += n0 * v0.x + n1 * v1.x;
            ay += n0 * v0.y + n1 * v1.y;
        }
    }
    if (j < end) {
        int s0 = col[j];
        float n0 = nrm[s0];
        if (act) {
            float2 v0 = *reinterpret_cast<const float2*>(hin + (size_t)s0 * CDIM + c2);
            ax += n0 * v0.x;
            ay += n0 * v0.y;
        }
    }
    if (act) {
        float nd = nrm[n];
        *reinterpret_cast<float2*>(hout + (size_t)n * CDIM + c2) = make_float2(nd * ax, nd * ay);
    }
}

// ---------------- final sigmoid-gated combine (float2 lanes) ----------------
__global__ void final_kernel(const float* __restrict__ H, const float* __restrict__ s,
                             float* __restrict__ out, int N) {
    int t = blockIdx.x * blockDim.x + threadIdx.x;
    int n = t >> 5;
    int lane = t & 31;
    if (n >= N) return;

    const bool act = (lane < CDIM / 2);
    const int  c2  = lane * 2;
    float sx = act ? s[c2] : 0.f;
    float sy = act ? s[c2 + 1] : 0.f;

    float ax = 0.f, ay = 0.f;
    size_t plane = (size_t)N * CDIM;
    const float* base = H + (size_t)n * CDIM;

#pragma unroll
    for (int k = 0; k <= KHOP; k++) {
        float2 h = act ? *reinterpret_cast<const float2*>(base + (size_t)k * plane + c2)
                       : make_float2(0.f, 0.f);
        float dot = h.x * sx + h.y * sy;
#pragma unroll
        for (int off = 16; off; off >>= 1)
            dot += __shfl_xor_sync(0xffffffffu, dot, off);
        float S = 1.f / (1.f + __expf(-dot));
        ax += S * h.x;
        ay += S * h.y;
    }
    if (act)
        *reinterpret_cast<float2*>(out + (size_t)n * CDIM + c2) = make_float2(ax, ay);
}

// ---------------- launch ----------------
extern "C" void kernel_launch(void* const* d_in, const int* in_sizes, int n_in,
                              void* d_out, int out_size) {
    const float* feats = (const float*)d_in[0];
    const float* W1    = (const float*)d_in[1];
    const float* b1    = (const float*)d_in[2];
    const float* W2    = (const float*)d_in[3];
    const float* b2    = (const float*)d_in[4];
    const float* svec  = (const float*)d_in[5];
    const int*   src   = (const int*)d_in[6];
    const int*   dst   = (const int*)d_in[7];
    float* out = (float*)d_out;

    const int N = in_sizes[0] / INDIM;
    const int E = in_sizes[6];

    void *pv;
    cudaGetSymbolAddress(&pv, g_x1);     float*    x1     = (float*)pv;
    cudaGetSymbolAddress(&pv, g_H);      float*    H      = (float*)pv;
    cudaGetSymbolAddress(&pv, g_norm);   float*    nrm    = (float*)pv;
    cudaGetSymbolAddress(&pv, g_deg);    int*      deg    = (int*)pv;
    cudaGetSymbolAddress(&pv, g_rowptr); int*      rowptr = (int*)pv;
    cudaGetSymbolAddress(&pv, g_cursor); int*      cursor = (int*)pv;
    cudaGetSymbolAddress(&pv, g_bsum);   int*      bsum   = (int*)pv;
    cudaGetSymbolAddress(&pv, g_col);    int*      col    = (int*)pv;
    cudaGetSymbolAddress(&pv, g_w1h);    uint32_t* w1h    = (uint32_t*)pv;
    cudaGetSymbolAddress(&pv, g_w1l);    uint32_t* w1l    = (uint32_t*)pv;
    cudaGetSymbolAddress(&pv, g_w2h);    uint32_t* w2h    = (uint32_t*)pv;
    cudaGetSymbolAddress(&pv, g_w2l);    uint32_t* w2l    = (uint32_t*)pv;

    const size_t plane = (size_t)N * CDIM;
    const int nb = (N + 511) / 512;

    // 0) pre-decompose weights to tf32 hi/lo
    decomp_kernel<<<(INDIM * HIDD + 255) / 256, 256>>>(W1, w1h, w1l, INDIM * HIDD);
    decomp_kernel<<<(HIDD * CDIM + 255) / 256, 256>>>(W2, w2h, w2l, HIDD * CDIM);

    // 1) x1 = relu(feats @ W1 + b1)   [tensor cores, 3xTF32]
    {
        dim3 grid(HIDD / 128, (N + TBM - 1) / TBM);
        gemm_tf32<128, true><<<grid, 256>>>(feats, w1h, w1l, b1, x1, N, HIDD, INDIM);
    }
    // 2) H[0] = x1 @ W2 + b2          [tensor cores, 3xTF32]
    {
        dim3 grid(1, (N + TBM - 1) / TBM);
        gemm_tf32<64, false><<<grid, 256>>>(x1, w2h, w2l, b2, H, N, CDIM, HIDD);
    }
    // 3) CSR build
    zero_i_kernel<<<(N + 255) / 256, 256>>>(deg, N);
    hist_kernel<<<(E + 255) / 256, 256>>>(dst, deg, E);
    norm_kernel<<<(N + 255) / 256, 256>>>(deg, nrm, N);
    scan_block<<<nb, 512>>>(deg, rowptr, bsum, N);
    scan_sums<<<1, 1024>>>(bsum, nb);
    scan_finish<<<(N + 255) / 256, 256>>>(rowptr, bsum, cursor, N, E);
    fill_kernel<<<(E + 255) / 256, 256>>>(src, dst, cursor, col, E);

    // 4) K propagation hops
    for (int k = 1; k <= KHOP; k++) {
        const float* hin = H + (size_t)(k - 1) * plane;
        float* hout      = H + (size_t)k * plane;
        spmm_pull<<<(N * 32 + 255) / 256, 256>>>(rowptr, col, nrm, hin, hout, N);
    }

    // 5) sigmoid-gated combine
    final_kernel<<<(N * 32 + 255) / 256, 256>>>(H, svec, out, N);
}

// round 5
// speedup vs baseline: 1.2352x; 1.2352x over previous
#include <cuda_runtime.h>
#include <cstdint>

#define NMAX   100000
#define EMAX   1600000
#define CDIM   50
#define HIDD   256
#define INDIM  500
#define KHOP   10

// ---------------- static scratch (no allocations allowed) ----------------
static __device__ __align__(16) float    g_x1[(size_t)NMAX * HIDD];
static __device__ __align__(16) float    g_H [(size_t)(KHOP + 1) * NMAX * CDIM];
static __device__ float    g_norm[NMAX];
static __device__ int      g_deg   [NMAX];
static __device__ int      g_rowptr[NMAX + 1];
static __device__ int      g_cursor[NMAX];
static __device__ int      g_bsum  [1024];
static __device__ int      g_col   [EMAX];
static __device__ __align__(16) uint32_t g_w1h[INDIM * HIDD];
static __device__ __align__(16) uint32_t g_w1l[INDIM * HIDD];
static __device__ __align__(16) uint32_t g_w2h[HIDD * 64];   // padded ldb=64
static __device__ __align__(16) uint32_t g_w2l[HIDD * 64];

// ================= TF32 helpers =================
__device__ __forceinline__ void f2tf32(float x, uint32_t& hi, uint32_t& lo) {
    asm("cvt.rna.tf32.f32 %0, %1;" : "=r"(hi) : "f"(x));
    float r = x - __uint_as_float(hi);
    asm("cvt.rna.tf32.f32 %0, %1;" : "=r"(lo) : "f"(r));
}

__device__ __forceinline__ void mma_tf32(float* c, const uint32_t* a, const uint32_t* b) {
    asm volatile(
        "mma.sync.aligned.m16n8k8.row.col.f32.tf32.tf32.f32 "
        "{%0,%1,%2,%3}, {%4,%5,%6,%7}, {%8,%9}, {%0,%1,%2,%3};"
        : "+f"(c[0]), "+f"(c[1]), "+f"(c[2]), "+f"(c[3])
        : "r"(a[0]), "r"(a[1]), "r"(a[2]), "r"(a[3]), "r"(b[0]), "r"(b[1]));
}

__device__ __forceinline__ void cp_async16(uint32_t dst, const void* src, int sz) {
    asm volatile("cp.async.ca.shared.global [%0], [%1], 16, %2;"
                 :: "r"(dst), "l"(src), "r"(sz));
}
#define CP_COMMIT() asm volatile("cp.async.commit_group;")
#define CP_WAIT1()  asm volatile("cp.async.wait_group 1;")
#define CP_WAIT0()  asm volatile("cp.async.wait_group 0;")

// decompose fp32 weights -> tf32 hi/lo planes (once, tiny)
__global__ void decomp_kernel(const float* __restrict__ W,
                              uint32_t* __restrict__ Wh, uint32_t* __restrict__ Wl, int n) {
    int i = blockIdx.x * blockDim.x + threadIdx.x;
    if (i < n) { uint32_t h, l; f2tf32(W[i], h, l); Wh[i] = h; Wl[i] = l; }
}

// decompose with column padding: W [K][N] -> planes [K][ldp], zero-padded
__global__ void decomp_pad_kernel(const float* __restrict__ W,
                                  uint32_t* __restrict__ Wh, uint32_t* __restrict__ Wl,
                                  int K, int N, int ldp) {
    int i = blockIdx.x * blockDim.x + threadIdx.x;
    if (i >= K * ldp) return;
    int r = i / ldp, c = i % ldp;
    float x = (c < N) ? W[r * N + c] : 0.f;
    uint32_t h, l; f2tf32(x, h, l);
    Wh[i] = h; Wl[i] = l;
}

// ================= cp.async double-buffered 3xTF32 GEMM =================
// C = op(A @ B + bias). A:[M,K] fp32 row, B pre-decomposed u32 hi/lo [K,ldb] row.
// Block tile 128 x TBN x 16, 256 threads = 8 warps (2 x 4), warp tile 64 x (TBN/4).
#define TBM 128
#define TBK 16
#define AST 20          // A smem row stride in floats (bank-conflict-free magic)

template <int TBN, bool RELU>
__global__ __launch_bounds__(256)
void gemm_tf32_cp(const float* __restrict__ A,
                  const uint32_t* __restrict__ Bhg, const uint32_t* __restrict__ Blg,
                  const float* __restrict__ bias, float* __restrict__ C,
                  int M, int N, int K, int ldb) {
    constexpr int NI  = TBN / 32;
    constexpr int BST = TBN + 8;    // B smem row stride (u32)

    extern __shared__ uint8_t dyn[];
    float*    As = (float*)dyn;                           // [2][TBM][AST]
    uint32_t* Bh = (uint32_t*)(dyn + 2 * TBM * AST * 4);  // [2][TBK][BST]
    uint32_t* Bl = Bh + 2 * TBK * BST;

    const uint32_t sA  = (uint32_t)__cvta_generic_to_shared(As);
    const uint32_t sBh = (uint32_t)__cvta_generic_to_shared(Bh);
    const uint32_t sBl = (uint32_t)__cvta_generic_to_shared(Bl);

    const int tid  = threadIdx.x;
    const int lane = tid & 31;
    const int wid  = tid >> 5;
    const int wm   = (wid & 1) * 64;
    const int wn   = (wid >> 1) * (TBN / 4);
    const int g    = lane >> 2;
    const int tg   = lane & 3;
    const int row0 = blockIdx.y * TBM;
    const int col0 = blockIdx.x * TBN;

    float acc[4][NI][4];
#pragma unroll
    for (int i = 0; i < 4; i++)
#pragma unroll
        for (int j = 0; j < NI; j++)
#pragma unroll
            for (int q = 0; q < 4; q++) acc[i][j][q] = 0.f;

    auto load_tile = [&](int buf, int kt) {
        // A: TBM x TBK floats, 16B chunks (4 floats), zfill for M/K tails
#pragma unroll
        for (int q = 0; q < (TBM * TBK / 4 + 255) / 256; q++) {
            int chunk = tid + q * 256;
            if (chunk < TBM * TBK / 4) {
                int r = chunk >> 2, c = (chunk & 3) << 2;
                int gr = row0 + r, gc = kt + c;
                int vf = (gr < M) ? (K - gc) : 0;
                vf = vf < 0 ? 0 : (vf > 4 ? 4 : vf);
                const float* src = A + (size_t)(gr < M ? gr : 0) * K + (gc < K ? gc : 0);
                cp_async16(sA + (uint32_t)(((buf * TBM + r) * AST + c) * 4), src, vf * 4);
            }
        }
        // B hi/lo: TBK x TBN u32 each, zfill for K tail (cols pre-padded/aligned)
#pragma unroll
        for (int q = 0; q < (TBK * (TBN / 4) + 255) / 256; q++) {
            int chunk = tid + q * 256;
            if (chunk < TBK * (TBN / 4)) {
                int r = chunk / (TBN / 4), c = (chunk % (TBN / 4)) << 2;
                int gk = kt + r;
                int sz = (gk < K) ? 16 : 0;
                size_t off = (size_t)(gk < K ? gk : 0) * ldb + col0 + c;
                uint32_t so = (uint32_t)(((buf * TBK + r) * BST + c) * 4);
                cp_async16(sBh + so, Bhg + off, sz);
                cp_async16(sBl + so, Blg + off, sz);
            }
        }
    };

    const int ktiles = (K + TBK - 1) / TBK;
    load_tile(0, 0);
    CP_COMMIT();

    int buf = 0;
    for (int t = 0; t < ktiles; t++) {
        if (t + 1 < ktiles) {
            load_tile(buf ^ 1, (t + 1) * TBK);
            CP_COMMIT();
            CP_WAIT1();
        } else {
            CP_WAIT0();
        }
        __syncthreads();

        const float*    ab = As + buf * TBM * AST;
        const uint32_t* hb = Bh + buf * TBK * BST;
        const uint32_t* lb = Bl + buf * TBK * BST;

#pragma unroll
        for (int ks = 0; ks < 2; ks++) {
            const int k0 = ks * 8;
            uint32_t ah[4][4], al[4][4], bh[NI][2], bl[NI][2];
#pragma unroll
            for (int mi = 0; mi < 4; mi++) {
                int m = wm + mi * 16;
                float x0 = ab[(m + g    ) * AST + k0 + tg    ];
                float x1 = ab[(m + g + 8) * AST + k0 + tg    ];
                float x2 = ab[(m + g    ) * AST + k0 + 4 + tg];
                float x3 = ab[(m + g + 8) * AST + k0 + 4 + tg];
                f2tf32(x0, ah[mi][0], al[mi][0]);
                f2tf32(x1, ah[mi][1], al[mi][1]);
                f2tf32(x2, ah[mi][2], al[mi][2]);
                f2tf32(x3, ah[mi][3], al[mi][3]);
            }
#pragma unroll
            for (int ni = 0; ni < NI; ni++) {
                int n = wn + ni * 8;
                bh[ni][0] = hb[(k0 + tg    ) * BST + n + g];
                bh[ni][1] = hb[(k0 + 4 + tg) * BST + n + g];
                bl[ni][0] = lb[(k0 + tg    ) * BST + n + g];
                bl[ni][1] = lb[(k0 + 4 + tg) * BST + n + g];
            }
#pragma unroll
            for (int mi = 0; mi < 4; mi++)
#pragma unroll
                for (int ni = 0; ni < NI; ni++) {
                    mma_tf32(acc[mi][ni], ah[mi], bh[ni]);
                    mma_tf32(acc[mi][ni], al[mi], bh[ni]);
                    mma_tf32(acc[mi][ni], ah[mi], bl[ni]);
                }
        }
        __syncthreads();
        buf ^= 1;
    }

    // ---- epilogue ----
#pragma unroll
    for (int mi = 0; mi < 4; mi++) {
#pragma unroll
        for (int ni = 0; ni < NI; ni++) {
            int c = col0 + wn + ni * 8 + 2 * tg;
            float bv0 = (c < N) ? bias[c] : 0.f;
            float bv1 = (c + 1 < N) ? bias[c + 1] : 0.f;
            int r0 = row0 + wm + mi * 16 + g;
            int r1 = r0 + 8;
            if (r0 < M) {
                float v0 = acc[mi][ni][0] + bv0;
                float v1 = acc[mi][ni][1] + bv1;
                if (RELU) { v0 = fmaxf(v0, 0.f); v1 = fmaxf(v1, 0.f); }
                if (c + 1 < N)
                    *reinterpret_cast<float2*>(C + (size_t)r0 * N + c) = make_float2(v0, v1);
                else if (c < N)
                    C[(size_t)r0 * N + c] = v0;
            }
            if (r1 < M) {
                float v2 = acc[mi][ni][2] + bv0;
                float v3 = acc[mi][ni][3] + bv1;
                if (RELU) { v2 = fmaxf(v2, 0.f); v3 = fmaxf(v3, 0.f); }
                if (c + 1 < N)
                    *reinterpret_cast<float2*>(C + (size_t)r1 * N + c) = make_float2(v2, v3);
                else if (c < N)
                    C[(size_t)r1 * N + c] = v2;
            }
        }
    }
}

// ---------------- CSR build helpers ----------------
__global__ void zero_i_kernel(int* __restrict__ p, int n) {
    int i = blockIdx.x * blockDim.x + threadIdx.x;
    if (i < n) p[i] = 0;
}

__global__ void hist_kernel(const int* __restrict__ dst, int* __restrict__ deg, int E) {
    int i = blockIdx.x * blockDim.x + threadIdx.x;
    if (i < E) atomicAdd(&deg[dst[i]], 1);
}

__global__ void norm_kernel(const int* __restrict__ deg, float* __restrict__ nrm, int n) {
    int i = blockIdx.x * blockDim.x + threadIdx.x;
    if (i < n) nrm[i] = rsqrtf((float)deg[i]);
}

__global__ void scan_block(const int* __restrict__ deg, int* __restrict__ rowptr,
                           int* __restrict__ bsum, int n) {
    __shared__ int sh[512];
    int tid = threadIdx.x;
    int gid = blockIdx.x * 512 + tid;
    int v = (gid < n) ? deg[gid] : 0;
    sh[tid] = v;
    __syncthreads();
    for (int off = 1; off < 512; off <<= 1) {
        int t = (tid >= off) ? sh[tid - off] : 0;
        __syncthreads();
        sh[tid] += t;
        __syncthreads();
    }
    if (gid < n) rowptr[gid] = sh[tid] - v;
    if (tid == 511) bsum[blockIdx.x] = sh[511];
}

__global__ void scan_sums(int* __restrict__ bsum, int nb) {
    __shared__ int sh[1024];
    int tid = threadIdx.x;
    int v = (tid < nb) ? bsum[tid] : 0;
    sh[tid] = v;
    __syncthreads();
    for (int off = 1; off < 1024; off <<= 1) {
        int t = (tid >= off) ? sh[tid - off] : 0;
        __syncthreads();
        sh[tid] += t;
        __syncthreads();
    }
    if (tid < nb) bsum[tid] = sh[tid] - v;
}

__global__ void scan_finish(int* __restrict__ rowptr, const int* __restrict__ bsum,
                            int* __restrict__ cursor, int n, int E) {
    int gid = blockIdx.x * blockDim.x + threadIdx.x;
    if (gid < n) {
        int r = rowptr[gid] + bsum[gid / 512];
        rowptr[gid] = r;
        cursor[gid] = r;
    }
    if (gid == 0) rowptr[n] = E;
}

__global__ void fill_kernel(const int* __restrict__ src, const int* __restrict__ dst,
                            int* __restrict__ cursor, int* __restrict__ col, int E) {
    int e = blockIdx.x * blockDim.x + threadIdx.x;
    if (e >= E) return;
    int pos = atomicAdd(&cursor[dst[e]], 1);
    col[pos] = src[e];
}

// ---------------- fused pull-gather hop (float2 lanes, 4-wide MLP) ----------------
__global__ void spmm_pull(const int* __restrict__ rowptr, const int* __restrict__ col,
                          const float* __restrict__ nrm,
                          const float* __restrict__ hin, float* __restrict__ hout,
                          int N) {
    int t = blockIdx.x * blockDim.x + threadIdx.x;
    int n = t >> 5;
    int lane = t & 31;
    if (n >= N) return;

    int beg = rowptr[n];
    int end = rowptr[n + 1];
    const bool act = (lane < CDIM / 2);
    const int  c2  = lane * 2;

    float ax = 0.f, ay = 0.f;
    int j = beg;
    for (; j + 3 < end; j += 4) {
        int s0 = col[j], s1 = col[j + 1], s2 = col[j + 2], s3 = col[j + 3];
        float n0 = nrm[s0], n1 = nrm[s1], n2 = nrm[s2], n3 = nrm[s3];
        if (act) {
            float2 v0 = *reinterpret_cast<const float2*>(hin + (size_t)s0 * CDIM + c2);
            float2 v1 = *reinterpret_cast<const float2*>(hin + (size_t)s1 * CDIM + c2);
            float2 v2 = *reinterpret_cast<const float2*>(hin + (size_t)s2 * CDIM + c2);
            float2 v3 = *reinterpret_cast<const float2*>(hin + (size_t)s3 * CDIM + c2);
            ax += n0 * v0.x + n1 * v1.x + n2 * v2.x + n3 * v3.x;
            ay += n0 * v0.y + n1 * v1.y + n2 * v2.y + n3 * v3.y;
        }
    }
    for (; j < end; j++) {
        int s0 = col[j];
        float n0 = nrm[s0];
        if (act) {
            float2 v0 = *reinterpret_cast<const float2*>(hin + (size_t)s0 * CDIM + c2);
            ax += n0 * v0.x;
            ay += n0 * v0.y;
        }
    }
    if (act) {
        float nd = nrm[n];
        *reinterpret_cast<float2*>(hout + (size_t)n * CDIM + c2) = make_float2(nd * ax, nd * ay);
    }
}

// ---------------- final sigmoid-gated combine ----------------
__global__ void final_kernel(const float* __restrict__ H, const float* __restrict__ s,
                             float* __restrict__ out, int N) {
    int t = blockIdx.x * blockDim.x + threadIdx.x;
    int n = t >> 5;
    int lane = t & 31;
    if (n >= N) return;

    const bool act = (lane < CDIM / 2);
    const int  c2  = lane * 2;
    float sx = act ? s[c2] : 0.f;
    float sy = act ? s[c2 + 1] : 0.f;

    float ax = 0.f, ay = 0.f;
    size_t plane = (size_t)N * CDIM;
    const float* base = H + (size_t)n * CDIM;

#pragma unroll
    for (int k = 0; k <= KHOP; k++) {
        float2 h = act ? *reinterpret_cast<const float2*>(base + (size_t)k * plane + c2)
                       : make_float2(0.f, 0.f);
        float dot = h.x * sx + h.y * sy;
#pragma unroll
        for (int off = 16; off; off >>= 1)
            dot += __shfl_xor_sync(0xffffffffu, dot, off);
        float S = 1.f / (1.f + __expf(-dot));
        ax += S * h.x;
        ay += S * h.y;
    }
    if (act)
        *reinterpret_cast<float2*>(out + (size_t)n * CDIM + c2) = make_float2(ax, ay);
}

// ---------------- launch ----------------
extern "C" void kernel_launch(void* const* d_in, const int* in_sizes, int n_in,
                              void* d_out, int out_size) {
    const float* feats = (const float*)d_in[0];
    const float* W1    = (const float*)d_in[1];
    const float* b1    = (const float*)d_in[2];
    const float* W2    = (const float*)d_in[3];
    const float* b2    = (const float*)d_in[4];
    const float* svec  = (const float*)d_in[5];
    const int*   src   = (const int*)d_in[6];
    const int*   dst   = (const int*)d_in[7];
    float* out = (float*)d_out;

    const int N = in_sizes[0] / INDIM;
    const int E = in_sizes[6];

    void *pv;
    cudaGetSymbolAddress(&pv, g_x1);     float*    x1     = (float*)pv;
    cudaGetSymbolAddress(&pv, g_H);      float*    H      = (float*)pv;
    cudaGetSymbolAddress(&pv, g_norm);   float*    nrm    = (float*)pv;
    cudaGetSymbolAddress(&pv, g_deg);    int*      deg    = (int*)pv;
    cudaGetSymbolAddress(&pv, g_rowptr); int*      rowptr = (int*)pv;
    cudaGetSymbolAddress(&pv, g_cursor); int*      cursor = (int*)pv;
    cudaGetSymbolAddress(&pv, g_bsum);   int*      bsum   = (int*)pv;
    cudaGetSymbolAddress(&pv, g_col);    int*      col    = (int*)pv;
    cudaGetSymbolAddress(&pv, g_w1h);    uint32_t* w1h    = (uint32_t*)pv;
    cudaGetSymbolAddress(&pv, g_w1l);    uint32_t* w1l    = (uint32_t*)pv;
    cudaGetSymbolAddress(&pv, g_w2h);    uint32_t* w2h    = (uint32_t*)pv;
    cudaGetSymbolAddress(&pv, g_w2l);    uint32_t* w2l    = (uint32_t*)pv;

    const size_t plane = (size_t)N * CDIM;
    const int nb = (N + 511) / 512;

    // dynamic smem sizes
    const int smem1 = 2 * TBM * AST * 4 + 2 * (2 * TBK * (128 + 8) * 4);  // 55296
    const int smem2 = 2 * TBM * AST * 4 + 2 * (2 * TBK * (64 + 8) * 4);   // 38912
    cudaFuncSetAttribute(gemm_tf32_cp<128, true>,
                         cudaFuncAttributeMaxDynamicSharedMemorySize, smem1);
    cudaFuncSetAttribute(gemm_tf32_cp<64, false>,
                         cudaFuncAttributeMaxDynamicSharedMemorySize, smem2);

    // 0) pre-decompose weights to tf32 hi/lo (W2 padded to ldb=64)
    decomp_kernel<<<(INDIM * HIDD + 255) / 256, 256>>>(W1, w1h, w1l, INDIM * HIDD);
    decomp_pad_kernel<<<(HIDD * 64 + 255) / 256, 256>>>(W2, w2h, w2l, HIDD, CDIM, 64);

    // 1) x1 = relu(feats @ W1 + b1)
    {
        dim3 grid(HIDD / 128, (N + TBM - 1) / TBM);
        gemm_tf32_cp<128, true><<<grid, 256, smem1>>>(feats, w1h, w1l, b1, x1,
                                                      N, HIDD, INDIM, HIDD);
    }
    // 2) H[0] = x1 @ W2 + b2
    {
        dim3 grid(1, (N + TBM - 1) / TBM);
        gemm_tf32_cp<64, false><<<grid, 256, smem2>>>(x1, w2h, w2l, b2, H,
                                                      N, CDIM, HIDD, 64);
    }
    // 3) CSR build
    zero_i_kernel<<<(N + 255) / 256, 256>>>(deg, N);
    hist_kernel<<<(E + 255) / 256, 256>>>(dst, deg, E);
    norm_kernel<<<(N + 255) / 256, 256>>>(deg, nrm, N);
    scan_block<<<nb, 512>>>(deg, rowptr, bsum, N);
    scan_sums<<<1, 1024>>>(bsum, nb);
    scan_finish<<<(N + 255) / 256, 256>>>(rowptr, bsum, cursor, N, E);
    fill_kernel<<<(E + 255) / 256, 256>>>(src, dst, cursor, col, E);

    // 4) K propagation hops
    for (int k = 1; k <= KHOP; k++) {
        const float* hin = H + (size_t)(k - 1) * plane;
        float* hout      = H + (size_t)k * plane;
        spmm_pull<<<(N * 32 + 255) / 256, 256>>>(rowptr, col, nrm, hin, hout, N);
    }

    // 5) sigmoid-gated combine
    final_kernel<<<(N * 32 + 255) / 256, 256>>>(H, svec, out, N);
}

// round 6
// speedup vs baseline: 1.4872x; 1.2040x over previous
#include <cuda_runtime.h>
#include <cuda_fp16.h>
#include <cstdint>

#define NMAX   100000
#define EMAX   1600000
#define CDIM   50
#define HLD    64            // padded H row stride (floats)
#define HIDD   256
#define INDIM  500
#define KHOP   10

// ---------------- static scratch (no allocations allowed) ----------------
static __device__ __align__(16) uint32_t g_x1h[(size_t)NMAX * (HIDD / 2)];  // x1 hi fp16x2
static __device__ __align__(16) uint32_t g_x1l[(size_t)NMAX * (HIDD / 2)];  // x1 lo fp16x2
static __device__ __align__(16) float    g_H [(size_t)(KHOP + 1) * NMAX * HLD];
static __device__ float    g_norm[NMAX];
static __device__ int      g_deg   [NMAX];
static __device__ int      g_rowptr[NMAX + 1];
static __device__ int      g_cursor[NMAX];
static __device__ int      g_bsum  [1024];
static __device__ int      g_col   [EMAX];
static __device__ __align__(16) uint32_t g_w1h[(INDIM / 2) * HIDD];  // W1 k-pair planes
static __device__ __align__(16) uint32_t g_w1l[(INDIM / 2) * HIDD];
static __device__ __align__(16) uint32_t g_w2h[(HIDD / 2) * 64];     // W2 padded ldp=64
static __device__ __align__(16) uint32_t g_w2l[(HIDD / 2) * 64];

// ================= fp16 2-term split helpers =================
__device__ __forceinline__ void split2(float x, float y, uint32_t& h2u, uint32_t& l2u) {
    __half2 h = __floats2half2_rn(x, y);
    float2 hf = __half22float2(h);
    __half2 l = __floats2half2_rn(x - hf.x, y - hf.y);
    h2u = *reinterpret_cast<uint32_t*>(&h);
    l2u = *reinterpret_cast<uint32_t*>(&l);
}

__device__ __forceinline__ void mma_f16(float* c, const uint32_t* a, const uint32_t* b) {
    asm volatile(
        "mma.sync.aligned.m16n8k16.row.col.f32.f16.f16.f32 "
        "{%0,%1,%2,%3}, {%4,%5,%6,%7}, {%8,%9}, {%0,%1,%2,%3};"
        : "+f"(c[0]), "+f"(c[1]), "+f"(c[2]), "+f"(c[3])
        : "r"(a[0]), "r"(a[1]), "r"(a[2]), "r"(a[3]), "r"(b[0]), "r"(b[1]));
}

__device__ __forceinline__ void cp_async16(uint32_t dst, const void* src, int sz) {
    asm volatile("cp.async.ca.shared.global [%0], [%1], 16, %2;"
                 :: "r"(dst), "l"(src), "r"(sz));
}
#define CP_COMMIT() asm volatile("cp.async.commit_group;")
#define CP_WAIT1()  asm volatile("cp.async.wait_group 1;")
#define CP_WAIT0()  asm volatile("cp.async.wait_group 0;")

// W [K][N] fp32 -> packed k-pair fp16 planes [K/2][ldp] (cols zero-padded)
__global__ void decomp_pair(const float* __restrict__ W,
                            uint32_t* __restrict__ Wh2, uint32_t* __restrict__ Wl2,
                            int K, int N, int ldp) {
    int i = blockIdx.x * blockDim.x + threadIdx.x;
    if (i >= (K / 2) * ldp) return;
    int k2 = i / ldp, c = i % ldp;
    float x = (c < N) ? W[(size_t)(2 * k2) * N + c] : 0.f;
    float y = (c < N) ? W[(size_t)(2 * k2 + 1) * N + c] : 0.f;
    uint32_t h, l; split2(x, y, h, l);
    Wh2[i] = h; Wl2[i] = l;
}

// ================= GEMM1: x1(split fp16) = relu(feats @ W1 + b1) =================
// A fp32 [M,500] (reg-staged LDG->cvt->STS), B packed planes. Tile 128x128x32.
#define TBM 128
#define TBK 32           // k per tile (k2 = 16)
#define ASU 20           // A smem u32 row stride (16 + 4 pad, conflict-free)
#define BST1 (128 + 8)

__global__ __launch_bounds__(256)
void gemm1_f16(const float* __restrict__ A,
               const uint32_t* __restrict__ Bh2g, const uint32_t* __restrict__ Bl2g,
               const float* __restrict__ bias,
               uint32_t* __restrict__ Ch2, uint32_t* __restrict__ Cl2,
               int M, int K) {
    constexpr int NI = 4;
    extern __shared__ uint8_t dyn[];
    uint32_t* Ah = (uint32_t*)dyn;                 // [2][128][ASU]
    uint32_t* Al = Ah + 2 * TBM * ASU;
    uint32_t* Bh = Al + 2 * TBM * ASU;             // [2][16][BST1]
    uint32_t* Bl = Bh + 2 * 16 * BST1;
    const uint32_t sBh = (uint32_t)__cvta_generic_to_shared(Bh);
    const uint32_t sBl = (uint32_t)__cvta_generic_to_shared(Bl);

    const int tid  = threadIdx.x;
    const int lane = tid & 31;
    const int wid  = tid >> 5;
    const int wm   = (wid & 1) * 64;
    const int wn   = (wid >> 1) * 32;
    const int g    = lane >> 2;
    const int tg   = lane & 3;
    const int row0 = blockIdx.y * TBM;
    const int col0 = blockIdx.x * 128;
    const int K2   = K / 2;            // 250

    float acc[4][NI][4];
#pragma unroll
    for (int i = 0; i < 4; i++)
#pragma unroll
        for (int j = 0; j < NI; j++)
#pragma unroll
            for (int q = 0; q < 4; q++) acc[i][j][q] = 0.f;

    float4 areg[4];
    auto ldgA = [&](int kt) {
#pragma unroll
        for (int q = 0; q < 4; q++) {
            int chunk = tid + q * 256;
            int r = chunk >> 3, c4 = (chunk & 7) * 4;
            int gr = row0 + r, gk = kt + c4;
            float4 v = make_float4(0.f, 0.f, 0.f, 0.f);
            if (gr < M) {
                if (gk + 3 < K) {
                    v = *reinterpret_cast<const float4*>(A + (size_t)gr * K + gk);
                } else if (gk < K) {
                    const float* p = A + (size_t)gr * K;
                    v.x = p[gk];
                    v.y = (gk + 1 < K) ? p[gk + 1] : 0.f;
                    v.z = (gk + 2 < K) ? p[gk + 2] : 0.f;
                    v.w = (gk + 3 < K) ? p[gk + 3] : 0.f;
                }
            }
            areg[q] = v;
        }
    };
    auto stsA = [&](int buf) {
#pragma unroll
        for (int q = 0; q < 4; q++) {
            int chunk = tid + q * 256;
            int r = chunk >> 3, c4 = (chunk & 7) * 4;
            uint32_t h01, l01, h23, l23;
            split2(areg[q].x, areg[q].y, h01, l01);
            split2(areg[q].z, areg[q].w, h23, l23);
            int base = (buf * TBM + r) * ASU + (c4 >> 1);
            *reinterpret_cast<uint2*>(&Ah[base]) = make_uint2(h01, h23);
            *reinterpret_cast<uint2*>(&Al[base]) = make_uint2(l01, l23);
        }
    };
    auto cpB = [&](int buf, int kt) {
        int k2t = kt >> 1;
#pragma unroll
        for (int q = 0; q < 4; q++) {
            int chunk = tid + q * 256;          // 1024 = 2 planes x 16 rows x 32 chunks
            int plane = chunk >> 9;
            int cc = chunk & 511;
            int r = cc >> 5, c4 = (cc & 31) * 4;
            int gk2 = k2t + r;
            int sz = (gk2 < K2) ? 16 : 0;
            const uint32_t* src = (plane ? Bl2g : Bh2g)
                                  + (size_t)(gk2 < K2 ? gk2 : 0) * HIDD + col0 + c4;
            uint32_t dst = (plane ? sBl : sBh) + (uint32_t)(((buf * 16 + r) * BST1 + c4) * 4);
            cp_async16(dst, src, sz);
        }
    };

    const int ktiles = (K + TBK - 1) / TBK;     // 16
    ldgA(0); stsA(0);
    cpB(0, 0); CP_COMMIT();

    int buf = 0;
    for (int t = 0; t < ktiles; t++) {
        if (t + 1 < ktiles) {
            ldgA((t + 1) * TBK);
            cpB(buf ^ 1, (t + 1) * TBK);
            CP_COMMIT();
            CP_WAIT1();
        } else {
            CP_WAIT0();
        }
        __syncthreads();

        const uint32_t* ab_h = Ah + buf * TBM * ASU;
        const uint32_t* ab_l = Al + buf * TBM * ASU;
        const uint32_t* bb_h = Bh + buf * 16 * BST1;
        const uint32_t* bb_l = Bl + buf * 16 * BST1;
#pragma unroll
        for (int ks = 0; ks < 2; ks++) {
            const int k2 = ks * 8;
            uint32_t ah[4][4], al[4][4], bh[NI][2], bl[NI][2];
#pragma unroll
            for (int mi = 0; mi < 4; mi++) {
                int m = wm + mi * 16;
                ah[mi][0] = ab_h[(m + g    ) * ASU + k2 + tg    ];
                ah[mi][1] = ab_h[(m + g + 8) * ASU + k2 + tg    ];
                ah[mi][2] = ab_h[(m + g    ) * ASU + k2 + 4 + tg];
                ah[mi][3] = ab_h[(m + g + 8) * ASU + k2 + 4 + tg];
                al[mi][0] = ab_l[(m + g    ) * ASU + k2 + tg    ];
                al[mi][1] = ab_l[(m + g + 8) * ASU + k2 + tg    ];
                al[mi][2] = ab_l[(m + g    ) * ASU + k2 + 4 + tg];
                al[mi][3] = ab_l[(m + g + 8) * ASU + k2 + 4 + tg];
            }
#pragma unroll
            for (int ni = 0; ni < NI; ni++) {
                int n = wn + ni * 8;
                bh[ni][0] = bb_h[(k2 + tg    ) * BST1 + n + g];
                bh[ni][1] = bb_h[(k2 + 4 + tg) * BST1 + n + g];
                bl[ni][0] = bb_l[(k2 + tg    ) * BST1 + n + g];
                bl[ni][1] = bb_l[(k2 + 4 + tg) * BST1 + n + g];
            }
#pragma unroll
            for (int mi = 0; mi < 4; mi++)
#pragma unroll
                for (int ni = 0; ni < NI; ni++) {
                    mma_f16(acc[mi][ni], ah[mi], bh[ni]);
                    mma_f16(acc[mi][ni], al[mi], bh[ni]);
                    mma_f16(acc[mi][ni], ah[mi], bl[ni]);
                }
        }
        if (t + 1 < ktiles) stsA(buf ^ 1);
        __syncthreads();
        buf ^= 1;
    }

    // epilogue: bias + relu, write split fp16 planes (x1 k-pairs for GEMM2)
#pragma unroll
    for (int mi = 0; mi < 4; mi++) {
#pragma unroll
        for (int ni = 0; ni < NI; ni++) {
            int c = col0 + wn + ni * 8 + 2 * tg;
            float bv0 = bias[c], bv1 = bias[c + 1];
            int r0 = row0 + wm + mi * 16 + g;
            int r1 = r0 + 8;
            if (r0 < M) {
                float v0 = fmaxf(acc[mi][ni][0] + bv0, 0.f);
                float v1 = fmaxf(acc[mi][ni][1] + bv1, 0.f);
                uint32_t h, l; split2(v0, v1, h, l);
                Ch2[(size_t)r0 * (HIDD / 2) + (c >> 1)] = h;
                Cl2[(size_t)r0 * (HIDD / 2) + (c >> 1)] = l;
            }
            if (r1 < M) {
                float v2 = fmaxf(acc[mi][ni][2] + bv0, 0.f);
                float v3 = fmaxf(acc[mi][ni][3] + bv1, 0.f);
                uint32_t h, l; split2(v2, v3, h, l);
                Ch2[(size_t)r1 * (HIDD / 2) + (c >> 1)] = h;
                Cl2[(size_t)r1 * (HIDD / 2) + (c >> 1)] = l;
            }
        }
    }
}

// ================= GEMM2: H0 = x1 @ W2 + b2 (all inputs pre-split) =================
#define BST2 (64 + 8)

__global__ __launch_bounds__(256)
void gemm2_f16(const uint32_t* __restrict__ Ah2g, const uint32_t* __restrict__ Al2g,
               const uint32_t* __restrict__ Bh2g, const uint32_t* __restrict__ Bl2g,
               const float* __restrict__ bias, float* __restrict__ C,
               int M) {
    constexpr int NI = 2;
    constexpr int K2 = HIDD / 2;       // 128
    extern __shared__ uint8_t dyn[];
    uint32_t* Ah = (uint32_t*)dyn;                 // [2][128][ASU]
    uint32_t* Al = Ah + 2 * TBM * ASU;
    uint32_t* Bh = Al + 2 * TBM * ASU;             // [2][16][BST2]
    uint32_t* Bl = Bh + 2 * 16 * BST2;
    const uint32_t sAh = (uint32_t)__cvta_generic_to_shared(Ah);
    const uint32_t sAl = (uint32_t)__cvta_generic_to_shared(Al);
    const uint32_t sBh = (uint32_t)__cvta_generic_to_shared(Bh);
    const uint32_t sBl = (uint32_t)__cvta_generic_to_shared(Bl);

    const int tid  = threadIdx.x;
    const int lane = tid & 31;
    const int wid  = tid >> 5;
    const int wm   = (wid & 1) * 64;
    const int wn   = (wid >> 1) * 16;
    const int g    = lane >> 2;
    const int tg   = lane & 3;
    const int row0 = blockIdx.y * TBM;

    float acc[4][NI][4];
#pragma unroll
    for (int i = 0; i < 4; i++)
#pragma unroll
        for (int j = 0; j < NI; j++)
#pragma unroll
            for (int q = 0; q < 4; q++) acc[i][j][q] = 0.f;

    auto load_tile = [&](int buf, int k2t) {
        // A planes: 128 rows x 4 chunks x 2 planes = 1024
#pragma unroll
        for (int q = 0; q < 4; q++) {
            int chunk = tid + q * 256;
            int plane = chunk >> 9;
            int cc = chunk & 511;
            int r = cc >> 2, c4 = (cc & 3) * 4;
            int gr = row0 + r;
            int sz = (gr < M) ? 16 : 0;
            const uint32_t* src = (plane ? Al2g : Ah2g)
                                  + (size_t)(gr < M ? gr : 0) * K2 + k2t + c4;
            uint32_t dst = (plane ? sAl : sAh) + (uint32_t)(((buf * TBM + r) * ASU + c4) * 4);
            cp_async16(dst, src, sz);
        }
        // B planes: 16 rows x 16 chunks x 2 planes = 512
#pragma unroll
        for (int q = 0; q < 2; q++) {
            int chunk = tid + q * 256;
            int plane = chunk >> 8;
            int cc = chunk & 255;
            int r = cc >> 4, c4 = (cc & 15) * 4;
            const uint32_t* src = (plane ? Bl2g : Bh2g) + (size_t)(k2t + r) * 64 + c4;
            uint32_t dst = (plane ? sBl : sBh) + (uint32_t)(((buf * 16 + r) * BST2 + c4) * 4);
            cp_async16(dst, src, 16);
        }
    };

    const int ktiles = HIDD / TBK;   // 8
    load_tile(0, 0); CP_COMMIT();

    int buf = 0;
    for (int t = 0; t < ktiles; t++) {
        if (t + 1 < ktiles) {
            load_tile(buf ^ 1, (t + 1) * (TBK / 2));
            CP_COMMIT();
            CP_WAIT1();
        } else {
            CP_WAIT0();
        }
        __syncthreads();

        const uint32_t* ab_h = Ah + buf * TBM * ASU;
        const uint32_t* ab_l = Al + buf * TBM * ASU;
        const uint32_t* bb_h = Bh + buf * 16 * BST2;
        const uint32_t* bb_l = Bl + buf * 16 * BST2;
#pragma unroll
        for (int ks = 0; ks < 2; ks++) {
            const int k2 = ks * 8;
            uint32_t ah[4][4], al[4][4], bh[NI][2], bl[NI][2];
#pragma unroll
            for (int mi = 0; mi < 4; mi++) {
                int m = wm + mi * 16;
                ah[mi][0] = ab_h[(m + g    ) * ASU + k2 + tg    ];
                ah[mi][1] = ab_h[(m + g + 8) * ASU + k2 + tg    ];
                ah[mi][2] = ab_h[(m + g    ) * ASU + k2 + 4 + tg];
                ah[mi][3] = ab_h[(m + g + 8) * ASU + k2 + 4 + tg];
                al[mi][0] = ab_l[(m + g    ) * ASU + k2 + tg    ];
                al[mi][1] = ab_l[(m + g + 8) * ASU + k2 + tg    ];
                al[mi][2] = ab_l[(m + g    ) * ASU + k2 + 4 + tg];
                al[mi][3] = ab_l[(m + g + 8) * ASU + k2 + 4 + tg];
            }
#pragma unroll
            for (int ni = 0; ni < NI; ni++) {
                int n = wn + ni * 8;
                bh[ni][0] = bb_h[(k2 + tg    ) * BST2 + n + g];
                bh[ni][1] = bb_h[(k2 + 4 + tg) * BST2 + n + g];
                bl[ni][0] = bb_l[(k2 + tg    ) * BST2 + n + g];
                bl[ni][1] = bb_l[(k2 + 4 + tg) * BST2 + n + g];
            }
#pragma unroll
            for (int mi = 0; mi < 4; mi++)
#pragma unroll
                for (int ni = 0; ni < NI; ni++) {
                    mma_f16(acc[mi][ni], ah[mi], bh[ni]);
                    mma_f16(acc[mi][ni], al[mi], bh[ni]);
                    mma_f16(acc[mi][ni], ah[mi], bl[ni]);
                }
        }
        __syncthreads();
        buf ^= 1;
    }

    // epilogue: bias, write H0 rows with stride HLD, cols < CDIM
#pragma unroll
    for (int mi = 0; mi < 4; mi++) {
#pragma unroll
        for (int ni = 0; ni < NI; ni++) {
            int c = wn + ni * 8 + 2 * tg;
            if (c + 1 >= CDIM && c >= CDIM) continue;
            float bv0 = (c < CDIM) ? bias[c] : 0.f;
            float bv1 = (c + 1 < CDIM) ? bias[c + 1] : 0.f;
            int r0 = row0 + wm + mi * 16 + g;
            int r1 = r0 + 8;
            if (r0 < M) {
                float v0 = acc[mi][ni][0] + bv0;
                float v1 = acc[mi][ni][1] + bv1;
                if (c + 1 < CDIM)
                    *reinterpret_cast<float2*>(C + (size_t)r0 * HLD + c) = make_float2(v0, v1);
                else if (c < CDIM)
                    C[(size_t)r0 * HLD + c] = v0;
            }
            if (r1 < M) {
                float v2 = acc[mi][ni][2] + bv0;
                float v3 = acc[mi][ni][3] + bv1;
                if (c + 1 < CDIM)
                    *reinterpret_cast<float2*>(C + (size_t)r1 * HLD + c) = make_float2(v2, v3);
                else if (c < CDIM)
                    C[(size_t)r1 * HLD + c] = v2;
            }
        }
    }
}

// ---------------- CSR build helpers ----------------
__global__ void zero_i_kernel(int* __restrict__ p, int n) {
    int i = blockIdx.x * blockDim.x + threadIdx.x;
    if (i < n) p[i] = 0;
}

__global__ void hist_kernel(const int* __restrict__ dst, int* __restrict__ deg, int E) {
    int i = blockIdx.x * blockDim.x + threadIdx.x;
    if (i < E) atomicAdd(&deg[dst[i]], 1);
}

__global__ void norm_kernel(const int* __restrict__ deg, float* __restrict__ nrm, int n) {
    int i = blockIdx.x * blockDim.x + threadIdx.x;
    if (i < n) nrm[i] = rsqrtf((float)deg[i]);
}

__global__ void scan_block(const int* __restrict__ deg, int* __restrict__ rowptr,
                           int* __restrict__ bsum, int n) {
    __shared__ int sh[512];
    int tid = threadIdx.x;
    int gid = blockIdx.x * 512 + tid;
    int v = (gid < n) ? deg[gid] : 0;
    sh[tid] = v;
    __syncthreads();
    for (int off = 1; off < 512; off <<= 1) {
        int t = (tid >= off) ? sh[tid - off] : 0;
        __syncthreads();
        sh[tid] += t;
        __syncthreads();
    }
    if (gid < n) rowptr[gid] = sh[tid] - v;
    if (tid == 511) bsum[blockIdx.x] = sh[511];
}

__global__ void scan_sums(int* __restrict__ bsum, int nb) {
    __shared__ int sh[1024];
    int tid = threadIdx.x;
    int v = (tid < nb) ? bsum[tid] : 0;
    sh[tid] = v;
    __syncthreads();
    for (int off = 1; off < 1024; off <<= 1) {
        int t = (tid >= off) ? sh[tid - off] : 0;
        __syncthreads();
        sh[tid] += t;
        __syncthreads();
    }
    if (tid < nb) bsum[tid] = sh[tid] - v;
}

__global__ void scan_finish(int* __restrict__ rowptr, const int* __restrict__ bsum,
                            int* __restrict__ cursor, int n, int E) {
    int gid = blockIdx.x * blockDim.x + threadIdx.x;
    if (gid < n) {
        int r = rowptr[gid] + bsum[gid / 512];
        rowptr[gid] = r;
        cursor[gid] = r;
    }
    if (gid == 0) rowptr[n] = E;
}

__global__ void fill_kernel(const int* __restrict__ src, const int* __restrict__ dst,
                            int* __restrict__ cursor, int* __restrict__ col, int E) {
    int e = blockIdx.x * blockDim.x + threadIdx.x;
    if (e >= E) return;
    int pos = atomicAdd(&cursor[dst[e]], 1);
    col[pos] = src[e];
}

// ---------------- fused pull-gather hop (padded rows, float2 lanes) ----------------
__global__ void spmm_pull(const int* __restrict__ rowptr, const int* __restrict__ col,
                          const float* __restrict__ nrm,
                          const float* __restrict__ hin, float* __restrict__ hout,
                          int N) {
    int t = blockIdx.x * blockDim.x + threadIdx.x;
    int n = t >> 5;
    int lane = t & 31;
    if (n >= N) return;

    int beg = rowptr[n];
    int end = rowptr[n + 1];
    const bool act = (lane < CDIM / 2);
    const int  c2  = lane * 2;

    float ax = 0.f, ay = 0.f;
    int j = beg;
    for (; j + 3 < end; j += 4) {
        int s0 = col[j], s1 = col[j + 1], s2 = col[j + 2], s3 = col[j + 3];
        float n0 = nrm[s0], n1 = nrm[s1], n2 = nrm[s2], n3 = nrm[s3];
        if (act) {
            float2 v0 = *reinterpret_cast<const float2*>(hin + (size_t)s0 * HLD + c2);
            float2 v1 = *reinterpret_cast<const float2*>(hin + (size_t)s1 * HLD + c2);
            float2 v2 = *reinterpret_cast<const float2*>(hin + (size_t)s2 * HLD + c2);
            float2 v3 = *reinterpret_cast<const float2*>(hin + (size_t)s3 * HLD + c2);
            ax += n0 * v0.x + n1 * v1.x + n2 * v2.x + n3 * v3.x;
            ay += n0 * v0.y + n1 * v1.y + n2 * v2.y + n3 * v3.y;
        }
    }
    for (; j < end; j++) {
        int s0 = col[j];
        float n0 = nrm[s0];
        if (act) {
            float2 v0 = *reinterpret_cast<const float2*>(hin + (size_t)s0 * HLD + c2);
            ax += n0 * v0.x;
            ay += n0 * v0.y;
        }
    }
    if (act) {
        float nd = nrm[n];
        *reinterpret_cast<float2*>(hout + (size_t)n * HLD + c2) = make_float2(nd * ax, nd * ay);
    }
}

// ---------------- final sigmoid-gated combine ----------------
__global__ void final_kernel(const float* __restrict__ H, const float* __restrict__ s,
                             float* __restrict__ out, int N) {
    int t = blockIdx.x * blockDim.x + threadIdx.x;
    int n = t >> 5;
    int lane = t & 31;
    if (n >= N) return;

    const bool act = (lane < CDIM / 2);
    const int  c2  = lane * 2;
    float sx = act ? s[c2] : 0.f;
    float sy = act ? s[c2 + 1] : 0.f;

    float ax = 0.f, ay = 0.f;
    size_t plane = (size_t)N * HLD;
    const float* base = H + (size_t)n * HLD;

#pragma unroll
    for (int k = 0; k <= KHOP; k++) {
        float2 h = act ? *reinterpret_cast<const float2*>(base + (size_t)k * plane + c2)
                       : make_float2(0.f, 0.f);
        float dot = h.x * sx + h.y * sy;
#pragma unroll
        for (int off = 16; off; off >>= 1)
            dot += __shfl_xor_sync(0xffffffffu, dot, off);
        float S = 1.f / (1.f + __expf(-dot));
        ax += S * h.x;
        ay += S * h.y;
    }
    if (act)
        *reinterpret_cast<float2*>(out + (size_t)n * CDIM + c2) = make_float2(ax, ay);
}

// ---------------- launch ----------------
extern "C" void kernel_launch(void* const* d_in, const int* in_sizes, int n_in,
                              void* d_out, int out_size) {
    const float* feats = (const float*)d_in[0];
    const float* W1    = (const float*)d_in[1];
    const float* b1    = (const float*)d_in[2];
    const float* W2    = (const float*)d_in[3];
    const float* b2    = (const float*)d_in[4];
    const float* svec  = (const float*)d_in[5];
    const int*   src   = (const int*)d_in[6];
    const int*   dst   = (const int*)d_in[7];
    float* out = (float*)d_out;

    const int N = in_sizes[0] / INDIM;
    const int E = in_sizes[6];

    void *pv;
    cudaGetSymbolAddress(&pv, g_x1h);    uint32_t* x1h    = (uint32_t*)pv;
    cudaGetSymbolAddress(&pv, g_x1l);    uint32_t* x1l    = (uint32_t*)pv;
    cudaGetSymbolAddress(&pv, g_H);      float*    H      = (float*)pv;
    cudaGetSymbolAddress(&pv, g_norm);   float*    nrm    = (float*)pv;
    cudaGetSymbolAddress(&pv, g_deg);    int*      deg    = (int*)pv;
    cudaGetSymbolAddress(&pv, g_rowptr); int*      rowptr = (int*)pv;
    cudaGetSymbolAddress(&pv, g_cursor); int*      cursor = (int*)pv;
    cudaGetSymbolAddress(&pv, g_bsum);   int*      bsum   = (int*)pv;
    cudaGetSymbolAddress(&pv, g_col);    int*      col    = (int*)pv;
    cudaGetSymbolAddress(&pv, g_w1h);    uint32_t* w1h    = (uint32_t*)pv;
    cudaGetSymbolAddress(&pv, g_w1l);    uint32_t* w1l    = (uint32_t*)pv;
    cudaGetSymbolAddress(&pv, g_w2h);    uint32_t* w2h    = (uint32_t*)pv;
    cudaGetSymbolAddress(&pv, g_w2l);    uint32_t* w2l    = (uint32_t*)pv;

    const size_t plane = (size_t)N * HLD;
    const int nb = (N + 511) / 512;

    const int smem1 = (2 * TBM * ASU * 4) * 2 + (2 * 16 * BST1 * 4) * 2;  // 151552
    const int smem2 = (2 * TBM * ASU * 4) * 2 + (2 * 16 * BST2 * 4) * 2;  // 100352
    cudaFuncSetAttribute(gemm1_f16, cudaFuncAttributeMaxDynamicSharedMemorySize, smem1);
    cudaFuncSetAttribute(gemm2_f16, cudaFuncAttributeMaxDynamicSharedMemorySize, smem2);

    // 0) pre-split weights into packed fp16 k-pair planes
    decomp_pair<<<((INDIM / 2) * HIDD + 255) / 256, 256>>>(W1, w1h, w1l, INDIM, HIDD, HIDD);
    decomp_pair<<<((HIDD / 2) * 64 + 255) / 256, 256>>>(W2, w2h, w2l, HIDD, CDIM, 64);

    // 1) x1 (split) = relu(feats @ W1 + b1)
    {
        dim3 grid(2, (N + TBM - 1) / TBM);
        gemm1_f16<<<grid, 256, smem1>>>(feats, w1h, w1l, b1, x1h, x1l, N, INDIM);
    }
    // 2) H0 = x1 @ W2 + b2   (stride-HLD output)
    {
        dim3 grid(1, (N + TBM - 1) / TBM);
        gemm2_f16<<<grid, 256, smem2>>>(x1h, x1l, w2h, w2l, b2, H, N);
    }
    // 3) CSR build
    zero_i_kernel<<<(N + 255) / 256, 256>>>(deg, N);
    hist_kernel<<<(E + 255) / 256, 256>>>(dst, deg, E);
    norm_kernel<<<(N + 255) / 256, 256>>>(deg, nrm, N);
    scan_block<<<nb, 512>>>(deg, rowptr, bsum, N);
    scan_sums<<<1, 1024>>>(bsum, nb);
    scan_finish<<<(N + 255) / 256, 256>>>(rowptr, bsum, cursor, N, E);
    fill_kernel<<<(E + 255) / 256, 256>>>(src, dst, cursor, col, E);

    // 4) K propagation hops
    for (int k = 1; k <= KHOP; k++) {
        const float* hin = H + (size_t)(k - 1) * plane;
        float* hout      = H + (size_t)k * plane;
        spmm_pull<<<(N * 32 + 255) / 256, 256>>>(rowptr, col, nrm, hin, hout, N);
    }

    // 5) sigmoid-gated combine
    final_kernel<<<(N * 32 + 255) / 256, 256>>>(H, svec, out, N);
}

// round 8
// speedup vs baseline: 1.5417x; 1.0366x over previous
#include <cuda_runtime.h>
#include <cuda_fp16.h>
#include <cstdint>

#define NMAX   100000
#define EMAX   1600000
#define CDIM   50
#define HLD    64            // padded H row stride (floats)
#define HIDD   256
#define INDIM  500
#define KHOP   10

// ---------------- static scratch (no allocations allowed) ----------------
static __device__ __align__(16) uint32_t g_x1h[(size_t)NMAX * (HIDD / 2)];  // x1 hi fp16x2
static __device__ __align__(16) uint32_t g_x1l[(size_t)NMAX * (HIDD / 2)];  // x1 lo fp16x2
static __device__ __align__(16) float    g_H [(size_t)(KHOP + 1) * NMAX * HLD];
static __device__ float    g_norm[NMAX];
static __device__ int      g_deg   [NMAX];
static __device__ int      g_rowptr[NMAX + 1];
static __device__ int      g_cursor[NMAX];
static __device__ int      g_bsum  [1024];
static __device__ int      g_col   [EMAX];
static __device__ __align__(16) uint32_t g_w1h[(INDIM / 2) * HIDD];  // W1 k-pair planes
static __device__ __align__(16) uint32_t g_w1l[(INDIM / 2) * HIDD];
static __device__ __align__(16) uint32_t g_w2h[(HIDD / 2) * 64];     // W2 padded ldp=64
static __device__ __align__(16) uint32_t g_w2l[(HIDD / 2) * 64];

// ================= fp16 2-term split helpers =================
__device__ __forceinline__ void split2(float x, float y, uint32_t& h2u, uint32_t& l2u) {
    __half2 h = __floats2half2_rn(x, y);
    float2 hf = __half22float2(h);
    __half2 l = __floats2half2_rn(x - hf.x, y - hf.y);
    h2u = *reinterpret_cast<uint32_t*>(&h);
    l2u = *reinterpret_cast<uint32_t*>(&l);
}

__device__ __forceinline__ void mma_f16(float* c, const uint32_t* a, const uint32_t* b) {
    asm volatile(
        "mma.sync.aligned.m16n8k16.row.col.f32.f16.f16.f32 "
        "{%0,%1,%2,%3}, {%4,%5,%6,%7}, {%8,%9}, {%0,%1,%2,%3};"
        : "+f"(c[0]), "+f"(c[1]), "+f"(c[2]), "+f"(c[3])
        : "r"(a[0]), "r"(a[1]), "r"(a[2]), "r"(a[3]), "r"(b[0]), "r"(b[1]));
}

__device__ __forceinline__ void cp_async16(uint32_t dst, const void* src, int sz) {
    asm volatile("cp.async.ca.shared.global [%0], [%1], 16, %2;"
                 :: "r"(dst), "l"(src), "r"(sz));
}
#define CP_COMMIT() asm volatile("cp.async.commit_group;")
#define CP_WAIT1()  asm volatile("cp.async.wait_group 1;")
#define CP_WAIT0()  asm volatile("cp.async.wait_group 0;")

// W [K][N] fp32 -> packed k-pair fp16 planes [K/2][ldp] (cols zero-padded)
__global__ void decomp_pair(const float* __restrict__ W,
                            uint32_t* __restrict__ Wh2, uint32_t* __restrict__ Wl2,
                            int K, int N, int ldp) {
    int i = blockIdx.x * blockDim.x + threadIdx.x;
    if (i >= (K / 2) * ldp) return;
    int k2 = i / ldp, c = i % ldp;
    float x = (c < N) ? W[(size_t)(2 * k2) * N + c] : 0.f;
    float y = (c < N) ? W[(size_t)(2 * k2 + 1) * N + c] : 0.f;
    uint32_t h, l; split2(x, y, h, l);
    Wh2[i] = h; Wl2[i] = l;
}

// ================= GEMM1: x1(split fp16) = relu(feats @ W1 + b1) =================
// Tile 64x128x32, 8 warps (2x4), warp tile 32x32. smem 110.6KB -> 2 CTA/SM.
#define TBM1 64
#define TBK  32           // k per tile (k2 = 16)
#define ASU  20           // A smem u32 row stride (16 + 4 pad, conflict-free)
#define BST1 (128 + 8)

__global__ __launch_bounds__(256)
void gemm1_f16(const float* __restrict__ A,
               const uint32_t* __restrict__ Bh2g, const uint32_t* __restrict__ Bl2g,
               const float* __restrict__ bias,
               uint32_t* __restrict__ Ch2, uint32_t* __restrict__ Cl2,
               int M, int K) {
    constexpr int NI = 4;
    extern __shared__ uint8_t dyn[];
    uint32_t* Ah = (uint32_t*)dyn;                 // [2][64][ASU]
    uint32_t* Al = Ah + 2 * TBM1 * ASU;
    uint32_t* Bh = Al + 2 * TBM1 * ASU;            // [2][16][BST1]
    uint32_t* Bl = Bh + 2 * 16 * BST1;
    const uint32_t sBh = (uint32_t)__cvta_generic_to_shared(Bh);
    const uint32_t sBl = (uint32_t)__cvta_generic_to_shared(Bl);

    const int tid  = threadIdx.x;
    const int lane = tid & 31;
    const int wid  = tid >> 5;
    const int wm   = (wid & 1) * 32;
    const int wn   = (wid >> 1) * 32;
    const int g    = lane >> 2;
    const int tg   = lane & 3;
    const int row0 = blockIdx.y * TBM1;
    const int col0 = blockIdx.x * 128;
    const int K2   = K / 2;            // 250

    float acc[2][NI][4];
#pragma unroll
    for (int i = 0; i < 2; i++)
#pragma unroll
        for (int j = 0; j < NI; j++)
#pragma unroll
            for (int q = 0; q < 4; q++) acc[i][j][q] = 0.f;

    float4 areg[2];
    auto ldgA = [&](int kt) {
#pragma unroll
        for (int q = 0; q < 2; q++) {
            int chunk = tid + q * 256;          // 512 chunks = 64 rows x 8 float4
            int r = chunk >> 3, c4 = (chunk & 7) * 4;
            int gr = row0 + r, gk = kt + c4;
            float4 v = make_float4(0.f, 0.f, 0.f, 0.f);
            if (gr < M) {
                if (gk + 3 < K) {
                    v = *reinterpret_cast<const float4*>(A + (size_t)gr * K + gk);
                } else if (gk < K) {
                    const float* p = A + (size_t)gr * K;
                    v.x = p[gk];
                    v.y = (gk + 1 < K) ? p[gk + 1] : 0.f;
                    v.z = (gk + 2 < K) ? p[gk + 2] : 0.f;
                    v.w = (gk + 3 < K) ? p[gk + 3] : 0.f;
                }
            }
            areg[q] = v;
        }
    };
    auto stsA = [&](int buf) {
#pragma unroll
        for (int q = 0; q < 2; q++) {
            int chunk = tid + q * 256;
            int r = chunk >> 3, c4 = (chunk & 7) * 4;
            uint32_t h01, l01, h23, l23;
            split2(areg[q].x, areg[q].y, h01, l01);
            split2(areg[q].z, areg[q].w, h23, l23);
            int base = (buf * TBM1 + r) * ASU + (c4 >> 1);
            *reinterpret_cast<uint2*>(&Ah[base]) = make_uint2(h01, h23);
            *reinterpret_cast<uint2*>(&Al[base]) = make_uint2(l01, l23);
        }
    };
    auto cpB = [&](int buf, int kt) {
        int k2t = kt >> 1;
#pragma unroll
        for (int q = 0; q < 4; q++) {
            int chunk = tid + q * 256;          // 1024 = 2 planes x 16 rows x 32 chunks
            int plane = chunk >> 9;
            int cc = chunk & 511;
            int r = cc >> 5, c4 = (cc & 31) * 4;
            int gk2 = k2t + r;
            int sz = (gk2 < K2) ? 16 : 0;
            const uint32_t* src = (plane ? Bl2g : Bh2g)
                                  + (size_t)(gk2 < K2 ? gk2 : 0) * HIDD + col0 + c4;
            uint32_t dst = (plane ? sBl : sBh) + (uint32_t)(((buf * 16 + r) * BST1 + c4) * 4);
            cp_async16(dst, src, sz);
        }
    };

    const int ktiles = (K + TBK - 1) / TBK;     // 16
    ldgA(0); stsA(0);
    cpB(0, 0); CP_COMMIT();

    int buf = 0;
    for (int t = 0; t < ktiles; t++) {
        if (t + 1 < ktiles) {
            ldgA((t + 1) * TBK);
            cpB(buf ^ 1, (t + 1) * TBK);
            CP_COMMIT();
            CP_WAIT1();
        } else {
            CP_WAIT0();
        }
        __syncthreads();

        const uint32_t* ab_h = Ah + buf * TBM1 * ASU;
        const uint32_t* ab_l = Al + buf * TBM1 * ASU;
        const uint32_t* bb_h = Bh + buf * 16 * BST1;
        const uint32_t* bb_l = Bl + buf * 16 * BST1;
#pragma unroll
        for (int ks = 0; ks < 2; ks++) {
            const int k2 = ks * 8;
            uint32_t ah[2][4], al[2][4], bh[NI][2], bl[NI][2];
#pragma unroll
            for (int mi = 0; mi < 2; mi++) {
                int m = wm + mi * 16;
                ah[mi][0] = ab_h[(m + g    ) * ASU + k2 + tg    ];
                ah[mi][1] = ab_h[(m + g + 8) * ASU + k2 + tg    ];
                ah[mi][2] = ab_h[(m + g    ) * ASU + k2 + 4 + tg];
                ah[mi][3] = ab_h[(m + g + 8) * ASU + k2 + 4 + tg];
                al[mi][0] = ab_l[(m + g    ) * ASU + k2 + tg    ];
                al[mi][1] = ab_l[(m + g + 8) * ASU + k2 + tg    ];
                al[mi][2] = ab_l[(m + g    ) * ASU + k2 + 4 + tg];
                al[mi][3] = ab_l[(m + g + 8) * ASU + k2 + 4 + tg];
            }
#pragma unroll
            for (int ni = 0; ni < NI; ni++) {
                int n = wn + ni * 8;
                bh[ni][0] = bb_h[(k2 + tg    ) * BST1 + n + g];
                bh[ni][1] = bb_h[(k2 + 4 + tg) * BST1 + n + g];
                bl[ni][0] = bb_l[(k2 + tg    ) * BST1 + n + g];
                bl[ni][1] = bb_l[(k2 + 4 + tg) * BST1 + n + g];
            }
#pragma unroll
            for (int mi = 0; mi < 2; mi++)
#pragma unroll
                for (int ni = 0; ni < NI; ni++) {
                    mma_f16(acc[mi][ni], ah[mi], bh[ni]);
                    mma_f16(acc[mi][ni], al[mi], bh[ni]);
                    mma_f16(acc[mi][ni], ah[mi], bl[ni]);
                }
        }
        if (t + 1 < ktiles) stsA(buf ^ 1);
        __syncthreads();
        buf ^= 1;
    }

    // epilogue: bias + relu, write split fp16 planes (x1 k-pairs for GEMM2)
#pragma unroll
    for (int mi = 0; mi < 2; mi++) {
#pragma unroll
        for (int ni = 0; ni < NI; ni++) {
            int c = col0 + wn + ni * 8 + 2 * tg;
            float bv0 = bias[c], bv1 = bias[c + 1];
            int r0 = row0 + wm + mi * 16 + g;
            int r1 = r0 + 8;
            if (r0 < M) {
                float v0 = fmaxf(acc[mi][ni][0] + bv0, 0.f);
                float v1 = fmaxf(acc[mi][ni][1] + bv1, 0.f);
                uint32_t h, l; split2(v0, v1, h, l);
                Ch2[(size_t)r0 * (HIDD / 2) + (c >> 1)] = h;
                Cl2[(size_t)r0 * (HIDD / 2) + (c >> 1)] = l;
            }
            if (r1 < M) {
                float v2 = fmaxf(acc[mi][ni][2] + bv0, 0.f);
                float v3 = fmaxf(acc[mi][ni][3] + bv1, 0.f);
                uint32_t h, l; split2(v2, v3, h, l);
                Ch2[(size_t)r1 * (HIDD / 2) + (c >> 1)] = h;
                Cl2[(size_t)r1 * (HIDD / 2) + (c >> 1)] = l;
            }
        }
    }
}

// ================= GEMM2: H0 = x1 @ W2 + b2 (all inputs pre-split) =================
#define TBM 128
#define BST2 (64 + 8)

__global__ __launch_bounds__(256)
void gemm2_f16(const uint32_t* __restrict__ Ah2g, const uint32_t* __restrict__ Al2g,
               const uint32_t* __restrict__ Bh2g, const uint32_t* __restrict__ Bl2g,
               const float* __restrict__ bias, float* __restrict__ C,
               int M) {
    constexpr int NI = 2;
    constexpr int K2 = HIDD / 2;       // 128
    extern __shared__ uint8_t dyn[];
    uint32_t* Ah = (uint32_t*)dyn;                 // [2][128][ASU]
    uint32_t* Al = Ah + 2 * TBM * ASU;
    uint32_t* Bh = Al + 2 * TBM * ASU;             // [2][16][BST2]
    uint32_t* Bl = Bh + 2 * 16 * BST2;
    const uint32_t sAh = (uint32_t)__cvta_generic_to_shared(Ah);
    const uint32_t sAl = (uint32_t)__cvta_generic_to_shared(Al);
    const uint32_t sBh = (uint32_t)__cvta_generic_to_shared(Bh);
    const uint32_t sBl = (uint32_t)__cvta_generic_to_shared(Bl);

    const int tid  = threadIdx.x;
    const int lane = tid & 31;
    const int wid  = tid >> 5;
    const int wm   = (wid & 1) * 64;
    const int wn   = (wid >> 1) * 16;
    const int g    = lane >> 2;
    const int tg   = lane & 3;
    const int row0 = blockIdx.y * TBM;

    float acc[4][NI][4];
#pragma unroll
    for (int i = 0; i < 4; i++)
#pragma unroll
        for (int j = 0; j < NI; j++)
#pragma unroll
            for (int q = 0; q < 4; q++) acc[i][j][q] = 0.f;

    auto load_tile = [&](int buf, int k2t) {
#pragma unroll
        for (int q = 0; q < 4; q++) {
            int chunk = tid + q * 256;
            int plane = chunk >> 9;
            int cc = chunk & 511;
            int r = cc >> 2, c4 = (cc & 3) * 4;
            int gr = row0 + r;
            int sz = (gr < M) ? 16 : 0;
            const uint32_t* src = (plane ? Al2g : Ah2g)
                                  + (size_t)(gr < M ? gr : 0) * K2 + k2t + c4;
            uint32_t dst = (plane ? sAl : sAh) + (uint32_t)(((buf * TBM + r) * ASU + c4) * 4);
            cp_async16(dst, src, sz);
        }
#pragma unroll
        for (int q = 0; q < 2; q++) {
            int chunk = tid + q * 256;
            int plane = chunk >> 8;
            int cc = chunk & 255;
            int r = cc >> 4, c4 = (cc & 15) * 4;
            const uint32_t* src = (plane ? Bl2g : Bh2g) + (size_t)(k2t + r) * 64 + c4;
            uint32_t dst = (plane ? sBl : sBh) + (uint32_t)(((buf * 16 + r) * BST2 + c4) * 4);
            cp_async16(dst, src, 16);
        }
    };

    const int ktiles = HIDD / TBK;   // 8
    load_tile(0, 0); CP_COMMIT();

    int buf = 0;
    for (int t = 0; t < ktiles; t++) {
        if (t + 1 < ktiles) {
            load_tile(buf ^ 1, (t + 1) * (TBK / 2));
            CP_COMMIT();
            CP_WAIT1();
        } else {
            CP_WAIT0();
        }
        __syncthreads();

        const uint32_t* ab_h = Ah + buf * TBM * ASU;
        const uint32_t* ab_l = Al + buf * TBM * ASU;
        const uint32_t* bb_h = Bh + buf * 16 * BST2;
        const uint32_t* bb_l = Bl + buf * 16 * BST2;
#pragma unroll
        for (int ks = 0; ks < 2; ks++) {
            const int k2 = ks * 8;
            uint32_t ah[4][4], al[4][4], bh[NI][2], bl[NI][2];
#pragma unroll
            for (int mi = 0; mi < 4; mi++) {
                int m = wm + mi * 16;
                ah[mi][0] = ab_h[(m + g    ) * ASU + k2 + tg    ];
                ah[mi][1] = ab_h[(m + g + 8) * ASU + k2 + tg    ];
                ah[mi][2] = ab_h[(m + g    ) * ASU + k2 + 4 + tg];
                ah[mi][3] = ab_h[(m + g + 8) * ASU + k2 + 4 + tg];
                al[mi][0] = ab_l[(m + g    ) * ASU + k2 + tg    ];
                al[mi][1] = ab_l[(m + g + 8) * ASU + k2 + tg    ];
                al[mi][2] = ab_l[(m + g    ) * ASU + k2 + 4 + tg];
                al[mi][3] = ab_l[(m + g + 8) * ASU + k2 + 4 + tg];
            }
#pragma unroll
            for (int ni = 0; ni < NI; ni++) {
                int n = wn + ni * 8;
                bh[ni][0] = bb_h[(k2 + tg    ) * BST2 + n + g];
                bh[ni][1] = bb_h[(k2 + 4 + tg) * BST2 + n + g];
                bl[ni][0] = bb_l[(k2 + tg    ) * BST2 + n + g];
                bl[ni][1] = bb_l[(k2 + 4 + tg) * BST2 + n + g];
            }
#pragma unroll
            for (int mi = 0; mi < 4; mi++)
#pragma unroll
                for (int ni = 0; ni < NI; ni++) {
                    mma_f16(acc[mi][ni], ah[mi], bh[ni]);
                    mma_f16(acc[mi][ni], al[mi], bh[ni]);
                    mma_f16(acc[mi][ni], ah[mi], bl[ni]);
                }
        }
        __syncthreads();
        buf ^= 1;
    }

#pragma unroll
    for (int mi = 0; mi < 4; mi++) {
#pragma unroll
        for (int ni = 0; ni < NI; ni++) {
            int c = wn + ni * 8 + 2 * tg;
            if (c >= CDIM) continue;
            float bv0 = bias[c];
            float bv1 = (c + 1 < CDIM) ? bias[c + 1] : 0.f;
            int r0 = row0 + wm + mi * 16 + g;
            int r1 = r0 + 8;
            if (r0 < M) {
                float v0 = acc[mi][ni][0] + bv0;
                float v1 = acc[mi][ni][1] + bv1;
                if (c + 1 < CDIM)
                    *reinterpret_cast<float2*>(C + (size_t)r0 * HLD + c) = make_float2(v0, v1);
                else
                    C[(size_t)r0 * HLD + c] = v0;
            }
            if (r1 < M) {
                float v2 = acc[mi][ni][2] + bv0;
                float v3 = acc[mi][ni][3] + bv1;
                if (c + 1 < CDIM)
                    *reinterpret_cast<float2*>(C + (size_t)r1 * HLD + c) = make_float2(v2, v3);
                else
                    C[(size_t)r1 * HLD + c] = v2;
            }
        }
    }
}

// ---------------- CSR build helpers ----------------
__global__ void zero_i_kernel(int* __restrict__ p, int n) {
    int i = blockIdx.x * blockDim.x + threadIdx.x;
    if (i < n) p[i] = 0;
}

__global__ void hist_kernel(const int* __restrict__ dst, int* __restrict__ deg, int E) {
    int i = blockIdx.x * blockDim.x + threadIdx.x;
    if (i < E) atomicAdd(&deg[dst[i]], 1);
}

__global__ void norm_kernel(const int* __restrict__ deg, float* __restrict__ nrm, int n) {
    int i = blockIdx.x * blockDim.x + threadIdx.x;
    if (i < n) nrm[i] = rsqrtf((float)deg[i]);
}

__global__ void scan_block(const int* __restrict__ deg, int* __restrict__ rowptr,
                           int* __restrict__ bsum, int n) {
    __shared__ int sh[512];
    int tid = threadIdx.x;
    int gid = blockIdx.x * 512 + tid;
    int v = (gid < n) ? deg[gid] : 0;
    sh[tid] = v;
    __syncthreads();
    for (int off = 1; off < 512; off <<= 1) {
        int t = (tid >= off) ? sh[tid - off] : 0;
        __syncthreads();
        sh[tid] += t;
        __syncthreads();
    }
    if (gid < n) rowptr[gid] = sh[tid] - v;
    if (tid == 511) bsum[blockIdx.x] = sh[511];
}

__global__ void scan_sums(int* __restrict__ bsum, int nb) {
    __shared__ int sh[1024];
    int tid = threadIdx.x;
    int v = (tid < nb) ? bsum[tid] : 0;
    sh[tid] = v;
    __syncthreads();
    for (int off = 1; off < 1024; off <<= 1) {
        int t = (tid >= off) ? sh[tid - off] : 0;
        __syncthreads();
        sh[tid] += t;
        __syncthreads();
    }
    if (tid < nb) bsum[tid] = sh[tid] - v;
}

__global__ void scan_finish(int* __restrict__ rowptr, const int* __restrict__ bsum,
                            int* __restrict__ cursor, int n, int E) {
    int gid = blockIdx.x * blockDim.x + threadIdx.x;
    if (gid < n) {
        int r = rowptr[gid] + bsum[gid / 512];
        rowptr[gid] = r;
        cursor[gid] = r;
    }
    if (gid == 0) rowptr[n] = E;
}

__global__ void fill_kernel(const int* __restrict__ src, const int* __restrict__ dst,
                            int* __restrict__ cursor, int* __restrict__ col, int E) {
    int e = blockIdx.x * blockDim.x + threadIdx.x;
    if (e >= E) return;
    int pos = atomicAdd(&cursor[dst[e]], 1);
    col[pos] = src[e];
}

// ---------------- fused pull-gather hop (padded rows, float2 lanes) ----------------
__global__ void spmm_pull(const int* __restrict__ rowptr, const int* __restrict__ col,
                          const float* __restrict__ nrm,
                          const float* __restrict__ hin, float* __restrict__ hout,
                          int N) {
    int t = blockIdx.x * blockDim.x + threadIdx.x;
    int n = t >> 5;
    int lane = t & 31;
    if (n >= N) return;

    int beg = rowptr[n];
    int end = rowptr[n + 1];
    const bool act = (lane < CDIM / 2);
    const int  c2  = lane * 2;

    float ax = 0.f, ay = 0.f;
    int j = beg;
    for (; j + 3 < end; j += 4) {
        int s0 = col[j], s1 = col[j + 1], s2 = col[j + 2], s3 = col[j + 3];
        float n0 = nrm[s0], n1 = nrm[s1], n2 = nrm[s2], n3 = nrm[s3];
        if (act) {
            float2 v0 = *reinterpret_cast<const float2*>(hin + (size_t)s0 * HLD + c2);
            float2 v1 = *reinterpret_cast<const float2*>(hin + (size_t)s1 * HLD + c2);
            float2 v2 = *reinterpret_cast<const float2*>(hin + (size_t)s2 * HLD + c2);
            float2 v3 = *reinterpret_cast<const float2*>(hin + (size_t)s3 * HLD + c2);
            ax += n0 * v0.x + n1 * v1.x + n2 * v2.x + n3 * v3.x;
            ay += n0 * v0.y + n1 * v1.y + n2 * v2.y + n3 * v3.y;
        }
    }
    for (; j < end; j++) {
        int s0 = col[j];
        float n0 = nrm[s0];
        if (act) {
            float2 v0 = *reinterpret_cast<const float2*>(hin + (size_t)s0 * HLD + c2);
            ax += n0 * v0.x;
            ay += n0 * v0.y;
        }
    }
    if (act) {
        float nd = nrm[n];
        *reinterpret_cast<float2*>(hout + (size_t)n * HLD + c2) = make_float2(nd * ax, nd * ay);
    }
}

// ---------------- final sigmoid-gated combine ----------------
__global__ void final_kernel(const float* __restrict__ H, const float* __restrict__ s,
                             float* __restrict__ out, int N) {
    int t = blockIdx.x * blockDim.x + threadIdx.x;
    int n = t >> 5;
    int lane = t & 31;
    if (n >= N) return;

    const bool act = (lane < CDIM / 2);
    const int  c2  = lane * 2;
    float sx = act ? s[c2] : 0.f;
    float sy = act ? s[c2 + 1] : 0.f;

    float ax = 0.f, ay = 0.f;
    size_t plane = (size_t)N * HLD;
    const float* base = H + (size_t)n * HLD;

#pragma unroll
    for (int k = 0; k <= KHOP; k++) {
        float2 h = act ? *reinterpret_cast<const float2*>(base + (size_t)k * plane + c2)
                       : make_float2(0.f, 0.f);
        float dot = h.x * sx + h.y * sy;
#pragma unroll
        for (int off = 16; off; off >>= 1)
            dot += __shfl_xor_sync(0xffffffffu, dot, off);
        float S = 1.f / (1.f + __expf(-dot));
        ax += S * h.x;
        ay += S * h.y;
    }
    if (act)
        *reinterpret_cast<float2*>(out + (size_t)n * CDIM + c2) = make_float2(ax, ay);
}

// ---------------- launch ----------------
extern "C" void kernel_launch(void* const* d_in, const int* in_sizes, int n_in,
                              void* d_out, int out_size) {
    const float* feats = (const float*)d_in[0];
    const float* W1    = (const float*)d_in[1];
    const float* b1    = (const float*)d_in[2];
    const float* W2    = (const float*)d_in[3];
    const float* b2    = (const float*)d_in[4];
    const float* svec  = (const float*)d_in[5];
    const int*   src   = (const int*)d_in[6];
    const int*   dst   = (const int*)d_in[7];
    float* out = (float*)d_out;

    const int N = in_sizes[0] / INDIM;
    const int E = in_sizes[6];

    void *pv;
    cudaGetSymbolAddress(&pv, g_x1h);    uint32_t* x1h    = (uint32_t*)pv;
    cudaGetSymbolAddress(&pv, g_x1l);    uint32_t* x1l    = (uint32_t*)pv;
    cudaGetSymbolAddress(&pv, g_H);      float*    H      = (float*)pv;
    cudaGetSymbolAddress(&pv, g_norm);   float*    nrm    = (float*)pv;
    cudaGetSymbolAddress(&pv, g_deg);    int*      deg    = (int*)pv;
    cudaGetSymbolAddress(&pv, g_rowptr); int*      rowptr = (int*)pv;
    cudaGetSymbolAddress(&pv, g_cursor); int*      cursor = (int*)pv;
    cudaGetSymbolAddress(&pv, g_bsum);   int*      bsum   = (int*)pv;
    cudaGetSymbolAddress(&pv, g_col);    int*      col    = (int*)pv;
    cudaGetSymbolAddress(&pv, g_w1h);    uint32_t* w1h    = (uint32_t*)pv;
    cudaGetSymbolAddress(&pv, g_w1l);    uint32_t* w1l    = (uint32_t*)pv;
    cudaGetSymbolAddress(&pv, g_w2h);    uint32_t* w2h    = (uint32_t*)pv;
    cudaGetSymbolAddress(&pv, g_w2l);    uint32_t* w2l    = (uint32_t*)pv;

    const size_t plane = (size_t)N * HLD;
    const int nb = (N + 511) / 512;

    const int smem1 = (2 * TBM1 * ASU * 4) * 2 + (2 * 16 * BST1 * 4) * 2;  // 110592
    const int smem2 = (2 * TBM  * ASU * 4) * 2 + (2 * 16 * BST2 * 4) * 2;  // 100352
    cudaFuncSetAttribute(gemm1_f16, cudaFuncAttributeMaxDynamicSharedMemorySize, smem1);
    cudaFuncSetAttribute(gemm2_f16, cudaFuncAttributeMaxDynamicSharedMemorySize, smem2);

    // 0) pre-split weights into packed fp16 k-pair planes
    decomp_pair<<<((INDIM / 2) * HIDD + 255) / 256, 256>>>(W1, w1h, w1l, INDIM, HIDD, HIDD);
    decomp_pair<<<((HIDD / 2) * 64 + 255) / 256, 256>>>(W2, w2h, w2l, HIDD, CDIM, 64);

    // 1) x1 (split) = relu(feats @ W1 + b1)   [64-row tiles, 2 CTA/SM]
    {
        dim3 grid(2, (N + TBM1 - 1) / TBM1);
        gemm1_f16<<<grid, 256, smem1>>>(feats, w1h, w1l, b1, x1h, x1l, N, INDIM);
    }
    // 2) H0 = x1 @ W2 + b2   (stride-HLD output)
    {
        dim3 grid(1, (N + TBM - 1) / TBM);
        gemm2_f16<<<grid, 256, smem2>>>(x1h, x1l, w2h, w2l, b2, H, N);
    }
    // 3) CSR build
    zero_i_kernel<<<(N + 255) / 256, 256>>>(deg, N);
    hist_kernel<<<(E + 255) / 256, 256>>>(dst, deg, E);
    norm_kernel<<<(N + 255) / 256, 256>>>(deg, nrm, N);
    scan_block<<<nb, 512>>>(deg, rowptr, bsum, N);
    scan_sums<<<1, 1024>>>(bsum, nb);
    scan_finish<<<(N + 255) / 256, 256>>>(rowptr, bsum, cursor, N, E);
    fill_kernel<<<(E + 255) / 256, 256>>>(src, dst, cursor, col, E);

    // 4) K propagation hops
    for (int k = 1; k <= KHOP; k++) {
        const float* hin = H + (size_t)(k - 1) * plane;
        float* hout      = H + (size_t)k * plane;
        spmm_pull<<<(N * 32 + 255) / 256, 256>>>(rowptr, col, nrm, hin, hout, N);
    }

    // 5) sigmoid-gated combine
    final_kernel<<<(N * 32 + 255) / 256, 256>>>(H, svec, out, N);
}

// round 9
// speedup vs baseline: 1.6354x; 1.0608x over previous
#include <cuda_runtime.h>
#include <cuda_fp16.h>
#include <cstdint>

#define NMAX   100000
#define EMAX   1600000
#define CDIM   50
#define HLD    64            // padded H row stride (floats)
#define HIDD   256
#define INDIM  500
#define KHOP   10

// ---------------- static scratch (no allocations allowed) ----------------
static __device__ __align__(16) float    g_H [(size_t)(KHOP + 1) * NMAX * HLD];
static __device__ float    g_norm[NMAX];
static __device__ int      g_deg   [NMAX];
static __device__ int      g_rowptr[NMAX + 1];
static __device__ int      g_cursor[NMAX];
static __device__ int      g_bsum  [1024];
static __device__ int      g_col   [EMAX];
static __device__ __align__(16) uint32_t g_w1h[(INDIM / 2) * HIDD];  // W1 k-pair planes
static __device__ __align__(16) uint32_t g_w1l[(INDIM / 2) * HIDD];
static __device__ __align__(16) uint32_t g_w2h[(HIDD / 2) * 64];     // W2 padded ldp=64
static __device__ __align__(16) uint32_t g_w2l[(HIDD / 2) * 64];

// ================= fp16 2-term split helpers =================
__device__ __forceinline__ void split2(float x, float y, uint32_t& h2u, uint32_t& l2u) {
    __half2 h = __floats2half2_rn(x, y);
    float2 hf = __half22float2(h);
    __half2 l = __floats2half2_rn(x - hf.x, y - hf.y);
    h2u = *reinterpret_cast<uint32_t*>(&h);
    l2u = *reinterpret_cast<uint32_t*>(&l);
}

__device__ __forceinline__ void mma_f16(float* c, const uint32_t* a, const uint32_t* b) {
    asm volatile(
        "mma.sync.aligned.m16n8k16.row.col.f32.f16.f16.f32 "
        "{%0,%1,%2,%3}, {%4,%5,%6,%7}, {%8,%9}, {%0,%1,%2,%3};"
        : "+f"(c[0]), "+f"(c[1]), "+f"(c[2]), "+f"(c[3])
        : "r"(a[0]), "r"(a[1]), "r"(a[2]), "r"(a[3]), "r"(b[0]), "r"(b[1]));
}

__device__ __forceinline__ void cp_async16(uint32_t dst, const void* src, int sz) {
    asm volatile("cp.async.ca.shared.global [%0], [%1], 16, %2;"
                 :: "r"(dst), "l"(src), "r"(sz));
}
#define CP_COMMIT() asm volatile("cp.async.commit_group;")
#define CP_WAIT1()  asm volatile("cp.async.wait_group 1;")
#define CP_WAIT0()  asm volatile("cp.async.wait_group 0;")

// W [K][N] fp32 -> packed k-pair fp16 planes [K/2][ldp] (cols zero-padded)
__global__ void decomp_pair(const float* __restrict__ W,
                            uint32_t* __restrict__ Wh2, uint32_t* __restrict__ Wl2,
                            int K, int N, int ldp) {
    int i = blockIdx.x * blockDim.x + threadIdx.x;
    if (i >= (K / 2) * ldp) return;
    int k2 = i / ldp, c = i % ldp;
    float x = (c < N) ? W[(size_t)(2 * k2) * N + c] : 0.f;
    float y = (c < N) ? W[(size_t)(2 * k2 + 1) * N + c] : 0.f;
    uint32_t h, l; split2(x, y, h, l);
    Wh2[i] = h; Wl2[i] = l;
}

// ================= fused MLP: H0 = relu(feats@W1 + b1) @ W2 + b2 =================
// CTA: 64 rows x 256 hidden cols, 8 warps (2x4), warp tile 32x64.
// Phase 1: x1 tile in regs (double-buffered split-fp16 pipeline).
// Transition: x1 -> smem (reuses B region).
// Phase 2: x1tile @ W2 from smem -> H0.
#define TBM1 64
#define TBK  32            // k per tile (k2 = 16)
#define ASU  20            // A smem u32 row stride
#define BSTF 264           // phase-1 B smem row stride (256 + 8)
#define X1ST 132           // x1 smem tile row stride (128 + 4)
#define W2ST 72            // phase-2 W2 smem row stride (64 + 8)

__global__ __launch_bounds__(256, 2)
void mlp_fused(const float* __restrict__ A,
               const uint32_t* __restrict__ Bh2g, const uint32_t* __restrict__ Bl2g,
               const float* __restrict__ bias1,
               const uint32_t* __restrict__ W2hg, const uint32_t* __restrict__ W2lg,
               const float* __restrict__ bias2,
               float* __restrict__ C, int M, int K) {
    extern __shared__ uint8_t dyn[];
    uint32_t* Ah = (uint32_t*)dyn;                 // [2][64][ASU]   (phase 1)
    uint32_t* Al = Ah + 2 * TBM1 * ASU;
    uint32_t* Bh = Al + 2 * TBM1 * ASU;            // [2][16][BSTF]  (phase 1)
    uint32_t* Bl = Bh + 2 * 16 * BSTF;
    // phase-2 aliases
    uint32_t* X1h = Bh;                            // [64][X1ST]
    uint32_t* X1l = Bl;
    uint32_t* W2h = Ah;                            // [2][16][W2ST]
    uint32_t* W2l = Ah + 2 * 16 * W2ST;

    const uint32_t sBh  = (uint32_t)__cvta_generic_to_shared(Bh);
    const uint32_t sBl  = (uint32_t)__cvta_generic_to_shared(Bl);
    const uint32_t sW2h = (uint32_t)__cvta_generic_to_shared(W2h);
    const uint32_t sW2l = (uint32_t)__cvta_generic_to_shared(W2l);

    const int tid  = threadIdx.x;
    const int lane = tid & 31;
    const int wid  = tid >> 5;
    const int g    = lane >> 2;
    const int tg   = lane & 3;
    const int row0 = blockIdx.x * TBM1;
    const int K2   = K / 2;                        // 250

    // ---------------- phase 1: warp tile 32x64 over 256 cols ----------------
    const int wm = (wid & 1) * 32;
    const int wn = (wid >> 1) * 64;

    float acc[2][8][4];
#pragma unroll
    for (int i = 0; i < 2; i++)
#pragma unroll
        for (int j = 0; j < 8; j++)
#pragma unroll
            for (int q = 0; q < 4; q++) acc[i][j][q] = 0.f;

    float4 areg[2];
    auto ldgA = [&](int kt) {
#pragma unroll
        for (int q = 0; q < 2; q++) {
            int chunk = tid + q * 256;          // 512 = 64 rows x 8 float4
            int r = chunk >> 3, c4 = (chunk & 7) * 4;
            int gr = row0 + r, gk = kt + c4;
            float4 v = make_float4(0.f, 0.f, 0.f, 0.f);
            if (gr < M) {
                if (gk + 3 < K) {
                    v = *reinterpret_cast<const float4*>(A + (size_t)gr * K + gk);
                } else if (gk < K) {
                    const float* p = A + (size_t)gr * K;
                    v.x = p[gk];
                    v.y = (gk + 1 < K) ? p[gk + 1] : 0.f;
                    v.z = (gk + 2 < K) ? p[gk + 2] : 0.f;
                    v.w = (gk + 3 < K) ? p[gk + 3] : 0.f;
                }
            }
            areg[q] = v;
        }
    };
    auto stsA = [&](int buf) {
#pragma unroll
        for (int q = 0; q < 2; q++) {
            int chunk = tid + q * 256;
            int r = chunk >> 3, c4 = (chunk & 7) * 4;
            uint32_t h01, l01, h23, l23;
            split2(areg[q].x, areg[q].y, h01, l01);
            split2(areg[q].z, areg[q].w, h23, l23);
            int base = (buf * TBM1 + r) * ASU + (c4 >> 1);
            *reinterpret_cast<uint2*>(&Ah[base]) = make_uint2(h01, h23);
            *reinterpret_cast<uint2*>(&Al[base]) = make_uint2(l01, l23);
        }
    };
    auto cpB = [&](int buf, int kt) {
        int k2t = kt >> 1;
#pragma unroll
        for (int q = 0; q < 8; q++) {
            int chunk = tid + q * 256;          // 2048 = 2 planes x 16 rows x 64 c4
            int plane = chunk >> 10;
            int cc = chunk & 1023;
            int r = cc >> 6, c4 = (cc & 63) * 4;
            int gk2 = k2t + r;
            int sz = (gk2 < K2) ? 16 : 0;
            const uint32_t* src = (plane ? Bl2g : Bh2g)
                                  + (size_t)(gk2 < K2 ? gk2 : 0) * HIDD + c4;
            uint32_t dst = (plane ? sBl : sBh) + (uint32_t)(((buf * 16 + r) * BSTF + c4) * 4);
            cp_async16(dst, src, sz);
        }
    };

    const int ktiles = (K + TBK - 1) / TBK;     // 16
    ldgA(0); stsA(0);
    cpB(0, 0); CP_COMMIT();

    int buf = 0;
    for (int t = 0; t < ktiles; t++) {
        if (t + 1 < ktiles) {
            ldgA((t + 1) * TBK);
            cpB(buf ^ 1, (t + 1) * TBK);
            CP_COMMIT();
            CP_WAIT1();
        } else {
            CP_WAIT0();
        }
        __syncthreads();

        const uint32_t* ab_h = Ah + buf * TBM1 * ASU;
        const uint32_t* ab_l = Al + buf * TBM1 * ASU;
        const uint32_t* bb_h = Bh + buf * 16 * BSTF;
        const uint32_t* bb_l = Bl + buf * 16 * BSTF;
#pragma unroll
        for (int ks = 0; ks < 2; ks++) {
            const int k2 = ks * 8;
            uint32_t ah[2][4], al[2][4];
#pragma unroll
            for (int mi = 0; mi < 2; mi++) {
                int m = wm + mi * 16;
                ah[mi][0] = ab_h[(m + g    ) * ASU + k2 + tg    ];
                ah[mi][1] = ab_h[(m + g + 8) * ASU + k2 + tg    ];
                ah[mi][2] = ab_h[(m + g    ) * ASU + k2 + 4 + tg];
                ah[mi][3] = ab_h[(m + g + 8) * ASU + k2 + 4 + tg];
                al[mi][0] = ab_l[(m + g    ) * ASU + k2 + tg    ];
                al[mi][1] = ab_l[(m + g + 8) * ASU + k2 + tg    ];
                al[mi][2] = ab_l[(m + g    ) * ASU + k2 + 4 + tg];
                al[mi][3] = ab_l[(m + g + 8) * ASU + k2 + 4 + tg];
            }
#pragma unroll
            for (int ni = 0; ni < 8; ni++) {
                int n = wn + ni * 8;
                uint32_t bh[2], bl[2];
                bh[0] = bb_h[(k2 + tg    ) * BSTF + n + g];
                bh[1] = bb_h[(k2 + 4 + tg) * BSTF + n + g];
                bl[0] = bb_l[(k2 + tg    ) * BSTF + n + g];
                bl[1] = bb_l[(k2 + 4 + tg) * BSTF + n + g];
#pragma unroll
                for (int mi = 0; mi < 2; mi++) {
                    mma_f16(acc[mi][ni], ah[mi], bh);
                    mma_f16(acc[mi][ni], al[mi], bh);
                    mma_f16(acc[mi][ni], ah[mi], bl);
                }
            }
        }
        if (t + 1 < ktiles) stsA(buf ^ 1);
        __syncthreads();
        buf ^= 1;
    }

    // ---------------- transition: bias1 + relu, x1 tile -> smem (split) ----------------
    // (last loop iter ended with __syncthreads(); B region free to overwrite)
#pragma unroll
    for (int mi = 0; mi < 2; mi++) {
#pragma unroll
        for (int ni = 0; ni < 8; ni++) {
            int c = wn + ni * 8 + 2 * tg;
            float bv0 = bias1[c], bv1 = bias1[c + 1];
            int rA = wm + mi * 16 + g;
            int rB = rA + 8;
            float v0 = fmaxf(acc[mi][ni][0] + bv0, 0.f);
            float v1 = fmaxf(acc[mi][ni][1] + bv1, 0.f);
            float v2 = fmaxf(acc[mi][ni][2] + bv0, 0.f);
            float v3 = fmaxf(acc[mi][ni][3] + bv1, 0.f);
            uint32_t h, l;
            split2(v0, v1, h, l);
            X1h[rA * X1ST + (c >> 1)] = h;
            X1l[rA * X1ST + (c >> 1)] = l;
            split2(v2, v3, h, l);
            X1h[rB * X1ST + (c >> 1)] = h;
            X1l[rB * X1ST + (c >> 1)] = l;
        }
    }
    __syncthreads();

    // ---------------- phase 2: H0(64x50) = x1tile(64x256) @ W2 ----------------
    const int wm2 = (wid & 1) * 32;
    const int wn2 = (wid >> 1) * 16;

    float acc2[2][2][4];
#pragma unroll
    for (int i = 0; i < 2; i++)
#pragma unroll
        for (int j = 0; j < 2; j++)
#pragma unroll
            for (int q = 0; q < 4; q++) acc2[i][j][q] = 0.f;

    auto loadW2 = [&](int b, int k2t) {
#pragma unroll
        for (int q = 0; q < 2; q++) {
            int chunk = tid + q * 256;          // 512 = 2 planes x 16 rows x 16 c4
            int plane = chunk >> 8;
            int cc = chunk & 255;
            int r = cc >> 4, c4 = (cc & 15) * 4;
            const uint32_t* src = (plane ? W2lg : W2hg) + (size_t)(k2t + r) * 64 + c4;
            uint32_t dst = (plane ? sW2l : sW2h) + (uint32_t)(((b * 16 + r) * W2ST + c4) * 4);
            cp_async16(dst, src, 16);
        }
    };

    loadW2(0, 0); CP_COMMIT();
    int buf2 = 0;
    for (int t = 0; t < 8; t++) {               // 8 k2-tiles of 16 (K=256)
        if (t + 1 < 8) {
            loadW2(buf2 ^ 1, (t + 1) * 16);
            CP_COMMIT();
            CP_WAIT1();
        } else {
            CP_WAIT0();
        }
        __syncthreads();

        const uint32_t* wb_h = W2h + buf2 * 16 * W2ST;
        const uint32_t* wb_l = W2l + buf2 * 16 * W2ST;
        const int k2base = t * 16;
#pragma unroll
        for (int ks = 0; ks < 2; ks++) {
            const int k2 = ks * 8;
            uint32_t ah[2][4], al[2][4], bh[2][2], bl[2][2];
#pragma unroll
            for (int mi = 0; mi < 2; mi++) {
                int m = wm2 + mi * 16;
                int kc = k2base + k2;
                ah[mi][0] = X1h[(m + g    ) * X1ST + kc + tg    ];
                ah[mi][1] = X1h[(m + g + 8) * X1ST + kc + tg    ];
                ah[mi][2] = X1h[(m + g    ) * X1ST + kc + 4 + tg];
                ah[mi][3] = X1h[(m + g + 8) * X1ST + kc + 4 + tg];
                al[mi][0] = X1l[(m + g    ) * X1ST + kc + tg    ];
                al[mi][1] = X1l[(m + g + 8) * X1ST + kc + tg    ];
                al[mi][2] = X1l[(m + g    ) * X1ST + kc + 4 + tg];
                al[mi][3] = X1l[(m + g + 8) * X1ST + kc + 4 + tg];
            }
#pragma unroll
            for (int ni = 0; ni < 2; ni++) {
                int n = wn2 + ni * 8;
                bh[ni][0] = wb_h[(k2 + tg    ) * W2ST + n + g];
                bh[ni][1] = wb_h[(k2 + 4 + tg) * W2ST + n + g];
                bl[ni][0] = wb_l[(k2 + tg    ) * W2ST + n + g];
                bl[ni][1] = wb_l[(k2 + 4 + tg) * W2ST + n + g];
            }
#pragma unroll
            for (int mi = 0; mi < 2; mi++)
#pragma unroll
                for (int ni = 0; ni < 2; ni++) {
                    mma_f16(acc2[mi][ni], ah[mi], bh[ni]);
                    mma_f16(acc2[mi][ni], al[mi], bh[ni]);
                    mma_f16(acc2[mi][ni], ah[mi], bl[ni]);
                }
        }
        __syncthreads();
        buf2 ^= 1;
    }

    // epilogue 2: bias2, write H0 (stride HLD, cols < CDIM)
#pragma unroll
    for (int mi = 0; mi < 2; mi++) {
#pragma unroll
        for (int ni = 0; ni < 2; ni++) {
            int c = wn2 + ni * 8 + 2 * tg;
            if (c >= CDIM) continue;
            float bv0 = bias2[c];
            float bv1 = (c + 1 < CDIM) ? bias2[c + 1] : 0.f;
            int r0 = row0 + wm2 + mi * 16 + g;
            int r1 = r0 + 8;
            if (r0 < M) {
                float v0 = acc2[mi][ni][0] + bv0;
                float v1 = acc2[mi][ni][1] + bv1;
                if (c + 1 < CDIM)
                    *reinterpret_cast<float2*>(C + (size_t)r0 * HLD + c) = make_float2(v0, v1);
                else
                    C[(size_t)r0 * HLD + c] = v0;
            }
            if (r1 < M) {
                float v2 = acc2[mi][ni][2] + bv0;
                float v3 = acc2[mi][ni][3] + bv1;
                if (c + 1 < CDIM)
                    *reinterpret_cast<float2*>(C + (size_t)r1 * HLD + c) = make_float2(v2, v3);
                else
                    C[(size_t)r1 * HLD + c] = v2;
            }
        }
    }
}

// ---------------- CSR build helpers ----------------
__global__ void zero_i_kernel(int* __restrict__ p, int n) {
    int i = blockIdx.x * blockDim.x + threadIdx.x;
    if (i < n) p[i] = 0;
}

__global__ void hist_kernel(const int* __restrict__ dst, int* __restrict__ deg, int E) {
    int i = blockIdx.x * blockDim.x + threadIdx.x;
    if (i < E) atomicAdd(&deg[dst[i]], 1);
}

__global__ void norm_kernel(const int* __restrict__ deg, float* __restrict__ nrm, int n) {
    int i = blockIdx.x * blockDim.x + threadIdx.x;
    if (i < n) nrm[i] = rsqrtf((float)deg[i]);
}

__global__ void scan_block(const int* __restrict__ deg, int* __restrict__ rowptr,
                           int* __restrict__ bsum, int n) {
    __shared__ int sh[512];
    int tid = threadIdx.x;
    int gid = blockIdx.x * 512 + tid;
    int v = (gid < n) ? deg[gid] : 0;
    sh[tid] = v;
    __syncthreads();
    for (int off = 1; off < 512; off <<= 1) {
        int t = (tid >= off) ? sh[tid - off] : 0;
        __syncthreads();
        sh[tid] += t;
        __syncthreads();
    }
    if (gid < n) rowptr[gid] = sh[tid] - v;
    if (tid == 511) bsum[blockIdx.x] = sh[511];
}

__global__ void scan_sums(int* __restrict__ bsum, int nb) {
    __shared__ int sh[1024];
    int tid = threadIdx.x;
    int v = (tid < nb) ? bsum[tid] : 0;
    sh[tid] = v;
    __syncthreads();
    for (int off = 1; off < 1024; off <<= 1) {
        int t = (tid >= off) ? sh[tid - off] : 0;
        __syncthreads();
        sh[tid] += t;
        __syncthreads();
    }
    if (tid < nb) bsum[tid] = sh[tid] - v;
}

__global__ void scan_finish(int* __restrict__ rowptr, const int* __restrict__ bsum,
                            int* __restrict__ cursor, int n, int E) {
    int gid = blockIdx.x * blockDim.x + threadIdx.x;
    if (gid < n) {
        int r = rowptr[gid] + bsum[gid / 512];
        rowptr[gid] = r;
        cursor[gid] = r;
    }
    if (gid == 0) rowptr[n] = E;
}

__global__ void fill_kernel(const int* __restrict__ src, const int* __restrict__ dst,
                            int* __restrict__ cursor, int* __restrict__ col, int E) {
    int e = blockIdx.x * blockDim.x + threadIdx.x;
    if (e >= E) return;
    int pos = atomicAdd(&cursor[dst[e]], 1);
    col[pos] = src[e];
}

// ---------------- fused pull-gather hop (padded rows, float2 lanes) ----------------
__global__ void spmm_pull(const int* __restrict__ rowptr, const int* __restrict__ col,
                          const float* __restrict__ nrm,
                          const float* __restrict__ hin, float* __restrict__ hout,
                          int N) {
    int t = blockIdx.x * blockDim.x + threadIdx.x;
    int n = t >> 5;
    int lane = t & 31;
    if (n >= N) return;

    int beg = rowptr[n];
    int end = rowptr[n + 1];
    const bool act = (lane < CDIM / 2);
    const int  c2  = lane * 2;

    float ax = 0.f, ay = 0.f;
    int j = beg;
    for (; j + 3 < end; j += 4) {
        int s0 = col[j], s1 = col[j + 1], s2 = col[j + 2], s3 = col[j + 3];
        float n0 = nrm[s0], n1 = nrm[s1], n2 = nrm[s2], n3 = nrm[s3];
        if (act) {
            float2 v0 = *reinterpret_cast<const float2*>(hin + (size_t)s0 * HLD + c2);
            float2 v1 = *reinterpret_cast<const float2*>(hin + (size_t)s1 * HLD + c2);
            float2 v2 = *reinterpret_cast<const float2*>(hin + (size_t)s2 * HLD + c2);
            float2 v3 = *reinterpret_cast<const float2*>(hin + (size_t)s3 * HLD + c2);
            ax += n0 * v0.x + n1 * v1.x + n2 * v2.x + n3 * v3.x;
            ay += n0 * v0.y + n1 * v1.y + n2 * v2.y + n3 * v3.y;
        }
    }
    for (; j < end; j++) {
        int s0 = col[j];
        float n0 = nrm[s0];
        if (act) {
            float2 v0 = *reinterpret_cast<const float2*>(hin + (size_t)s0 * HLD + c2);
            ax += n0 * v0.x;
            ay += n0 * v0.y;
        }
    }
    if (act) {
        float nd = nrm[n];
        *reinterpret_cast<float2*>(hout + (size_t)n * HLD + c2) = make_float2(nd * ax, nd * ay);
    }
}

// ---------------- final sigmoid-gated combine ----------------
__global__ void final_kernel(const float* __restrict__ H, const float* __restrict__ s,
                             float* __restrict__ out, int N) {
    int t = blockIdx.x * blockDim.x + threadIdx.x;
    int n = t >> 5;
    int lane = t & 31;
    if (n >= N) return;

    const bool act = (lane < CDIM / 2);
    const int  c2  = lane * 2;
    float sx = act ? s[c2] : 0.f;
    float sy = act ? s[c2 + 1] : 0.f;

    float ax = 0.f, ay = 0.f;
    size_t plane = (size_t)N * HLD;
    const float* base = H + (size_t)n * HLD;

#pragma unroll
    for (int k = 0; k <= KHOP; k++) {
        float2 h = act ? *reinterpret_cast<const float2*>(base + (size_t)k * plane + c2)
                       : make_float2(0.f, 0.f);
        float dot = h.x * sx + h.y * sy;
#pragma unroll
        for (int off = 16; off; off >>= 1)
            dot += __shfl_xor_sync(0xffffffffu, dot, off);
        float S = 1.f / (1.f + __expf(-dot));
        ax += S * h.x;
        ay += S * h.y;
    }
    if (act)
        *reinterpret_cast<float2*>(out + (size_t)n * CDIM + c2) = make_float2(ax, ay);
}

// ---------------- launch ----------------
extern "C" void kernel_launch(void* const* d_in, const int* in_sizes, int n_in,
                              void* d_out, int out_size) {
    const float* feats = (const float*)d_in[0];
    const float* W1    = (const float*)d_in[1];
    const float* b1    = (const float*)d_in[2];
    const float* W2    = (const float*)d_in[3];
    const float* b2    = (const float*)d_in[4];
    const float* svec  = (const float*)d_in[5];
    const int*   src   = (const int*)d_in[6];
    const int*   dst   = (const int*)d_in[7];
    float* out = (float*)d_out;

    const int N = in_sizes[0] / INDIM;
    const int E = in_sizes[6];

    void *pv;
    cudaGetSymbolAddress(&pv, g_H);      float*    H      = (float*)pv;
    cudaGetSymbolAddress(&pv, g_norm);   float*    nrm    = (float*)pv;
    cudaGetSymbolAddress(&pv, g_deg);    int*      deg    = (int*)pv;
    cudaGetSymbolAddress(&pv, g_rowptr); int*      rowptr = (int*)pv;
    cudaGetSymbolAddress(&pv, g_cursor); int*      cursor = (int*)pv;
    cudaGetSymbolAddress(&pv, g_bsum);   int*      bsum   = (int*)pv;
    cudaGetSymbolAddress(&pv, g_col);    int*      col    = (int*)pv;
    cudaGetSymbolAddress(&pv, g_w1h);    uint32_t* w1h    = (uint32_t*)pv;
    cudaGetSymbolAddress(&pv, g_w1l);    uint32_t* w1l    = (uint32_t*)pv;
    cudaGetSymbolAddress(&pv, g_w2h);    uint32_t* w2h    = (uint32_t*)pv;
    cudaGetSymbolAddress(&pv, g_w2l);    uint32_t* w2l    = (uint32_t*)pv;

    const size_t plane = (size_t)N * HLD;
    const int nb = (N + 511) / 512;

    // smem: A region 20480 B + B region 67584 B = 88064 B  -> 2 CTA/SM
    const int smemF = 2 * TBM1 * ASU * 4 * 2 + 2 * 16 * BSTF * 4 * 2;
    cudaFuncSetAttribute(mlp_fused, cudaFuncAttributeMaxDynamicSharedMemorySize, smemF);

    // 0) pre-split weights into packed fp16 k-pair planes
    decomp_pair<<<((INDIM / 2) * HIDD + 255) / 256, 256>>>(W1, w1h, w1l, INDIM, HIDD, HIDD);
    decomp_pair<<<((HIDD / 2) * 64 + 255) / 256, 256>>>(W2, w2h, w2l, HIDD, CDIM, 64);

    // 1+2) fused MLP -> H0
    {
        dim3 grid((N + TBM1 - 1) / TBM1);
        mlp_fused<<<grid, 256, smemF>>>(feats, w1h, w1l, b1, w2h, w2l, b2, H, N, INDIM);
    }
    // 3) CSR build
    zero_i_kernel<<<(N + 255) / 256, 256>>>(deg, N);
    hist_kernel<<<(E + 255) / 256, 256>>>(dst, deg, E);
    norm_kernel<<<(N + 255) / 256, 256>>>(deg, nrm, N);
    scan_block<<<nb, 512>>>(deg, rowptr, bsum, N);
    scan_sums<<<1, 1024>>>(bsum, nb);
    scan_finish<<<(N + 255) / 256, 256>>>(rowptr, bsum, cursor, N, E);
    fill_kernel<<<(E + 255) / 256, 256>>>(src, dst, cursor, col, E);

    // 4) K propagation hops
    for (int k = 1; k <= KHOP; k++) {
        const float* hin = H + (size_t)(k - 1) * plane;
        float* hout      = H + (size_t)k * plane;
        spmm_pull<<<(N * 32 + 255) / 256, 256>>>(rowptr, col, nrm, hin, hout, N);
    }

    // 5) sigmoid-gated combine
    final_kernel<<<(N * 32 + 255) / 256, 256>>>(H, svec, out, N);
}

// round 11
// speedup vs baseline: 1.7541x; 1.0725x over previous
#include <cuda_runtime.h>
#include <cuda_fp16.h>
#include <cstdint>

#define NMAX   100000
#define EMAX   1600000
#define CDIM   50
#define HLD    64            // padded H row stride (floats)
#define HIDD   256
#define INDIM  500
#define KHOP   10

// ---------------- static scratch (no allocations allowed) ----------------
static __device__ __align__(16) float    g_H [(size_t)(KHOP + 1) * NMAX * HLD];
static __device__ float    g_norm[NMAX];
static __device__ int      g_deg   [NMAX];
static __device__ int      g_rowptr[NMAX + 1];
static __device__ int      g_cursor[NMAX];
static __device__ int      g_bsum  [1024];
static __device__ int      g_col   [EMAX];
static __device__ __align__(16) uint32_t g_w1h[(INDIM / 2) * HIDD];  // W1 k-pair hi plane
static __device__ __align__(16) uint32_t g_w1l[(INDIM / 2) * HIDD];  // (written, unused)
static __device__ __align__(16) uint32_t g_w2h[(HIDD / 2) * 64];     // W2 padded ldp=64
static __device__ __align__(16) uint32_t g_w2l[(HIDD / 2) * 64];

// ================= fp16 split helpers =================
__device__ __forceinline__ void split2(float x, float y, uint32_t& h2u, uint32_t& l2u) {
    __half2 h = __floats2half2_rn(x, y);
    float2 hf = __half22float2(h);
    __half2 l = __floats2half2_rn(x - hf.x, y - hf.y);
    h2u = *reinterpret_cast<uint32_t*>(&h);
    l2u = *reinterpret_cast<uint32_t*>(&l);
}

__device__ __forceinline__ void mma_f16(float* c, const uint32_t* a, const uint32_t* b) {
    asm volatile(
        "mma.sync.aligned.m16n8k16.row.col.f32.f16.f16.f32 "
        "{%0,%1,%2,%3}, {%4,%5,%6,%7}, {%8,%9}, {%0,%1,%2,%3};"
        : "+f"(c[0]), "+f"(c[1]), "+f"(c[2]), "+f"(c[3])
        : "r"(a[0]), "r"(a[1]), "r"(a[2]), "r"(a[3]), "r"(b[0]), "r"(b[1]));
}

__device__ __forceinline__ void cp_async16(uint32_t dst, const void* src, int sz) {
    asm volatile("cp.async.ca.shared.global [%0], [%1], 16, %2;"
                 :: "r"(dst), "l"(src), "r"(sz));
}
#define CP_COMMIT() asm volatile("cp.async.commit_group;")
#define CP_WAIT1()  asm volatile("cp.async.wait_group 1;")
#define CP_WAIT0()  asm volatile("cp.async.wait_group 0;")

// W [K][N] fp32 -> packed k-pair fp16 planes [K/2][ldp] (cols zero-padded)
__global__ void decomp_pair(const float* __restrict__ W,
                            uint32_t* __restrict__ Wh2, uint32_t* __restrict__ Wl2,
                            int K, int N, int ldp) {
    int i = blockIdx.x * blockDim.x + threadIdx.x;
    if (i >= (K / 2) * ldp) return;
    int k2 = i / ldp, c = i % ldp;
    float x = (c < N) ? W[(size_t)(2 * k2) * N + c] : 0.f;
    float y = (c < N) ? W[(size_t)(2 * k2 + 1) * N + c] : 0.f;
    uint32_t h, l; split2(x, y, h, l);
    Wh2[i] = h; Wl2[i] = l;
}

// ================= fused MLP: H0 = relu(feats@W1 + b1) @ W2 + b2 =================
// Phase 1: 2-term (AhBh + AlBh) — W1 hi plane only. Phase 2: 3-term via smem x1,
// W2 double-buffered in 16-k2 tiles (local indices — round-10 OOB bug fixed).
#define TBM1 64
#define TBK  32            // k per tile (k2 = 16)
#define ASU  20            // A smem u32 row stride
#define BSTF 264           // phase-1 B smem row stride (256 + 8)
#define X1ST 132           // x1 smem tile row stride (128 + 4)
#define W2ST 72            // phase-2 W2 smem row stride (64 + 8)

__global__ __launch_bounds__(256, 2)
void mlp_fused(const float* __restrict__ A,
               const uint32_t* __restrict__ Bh2g,
               const float* __restrict__ bias1,
               const uint32_t* __restrict__ W2hg, const uint32_t* __restrict__ W2lg,
               const float* __restrict__ bias2,
               float* __restrict__ C, int M, int K) {
    extern __shared__ uint8_t dyn[];
    // phase-1 layout
    uint32_t* Ah = (uint32_t*)dyn;                 // [2][64][ASU]
    uint32_t* Al = Ah + 2 * TBM1 * ASU;
    uint32_t* Bh = Al + 2 * TBM1 * ASU;            // [2][16][BSTF] (hi only)
    // phase-2 layout (aliases region; phase-1 data dead by then)
    uint32_t* X1h = (uint32_t*)dyn;                // [64][X1ST]
    uint32_t* X1l = X1h + TBM1 * X1ST;
    uint32_t* W2h = X1l + TBM1 * X1ST;             // [2][16][W2ST]
    uint32_t* W2l = W2h + 2 * 16 * W2ST;           // [2][16][W2ST]

    const uint32_t sBh  = (uint32_t)__cvta_generic_to_shared(Bh);
    const uint32_t sW2h = (uint32_t)__cvta_generic_to_shared(W2h);
    const uint32_t sW2l = (uint32_t)__cvta_generic_to_shared(W2l);

    const int tid  = threadIdx.x;
    const int lane = tid & 31;
    const int wid  = tid >> 5;
    const int g    = lane >> 2;
    const int tg   = lane & 3;
    const int row0 = blockIdx.x * TBM1;
    const int K2   = K / 2;                        // 250

    // ---------------- phase 1: warp tile 32x64 over 256 cols ----------------
    const int wm = (wid & 1) * 32;
    const int wn = (wid >> 1) * 64;

    float acc[2][8][4];
#pragma unroll
    for (int i = 0; i < 2; i++)
#pragma unroll
        for (int j = 0; j < 8; j++)
#pragma unroll
            for (int q = 0; q < 4; q++) acc[i][j][q] = 0.f;

    float4 areg[2];
    auto ldgA = [&](int kt) {
#pragma unroll
        for (int q = 0; q < 2; q++) {
            int chunk = tid + q * 256;          // 512 = 64 rows x 8 float4
            int r = chunk >> 3, c4 = (chunk & 7) * 4;
            int gr = row0 + r, gk = kt + c4;
            float4 v = make_float4(0.f, 0.f, 0.f, 0.f);
            if (gr < M) {
                if (gk + 3 < K) {
                    v = *reinterpret_cast<const float4*>(A + (size_t)gr * K + gk);
                } else if (gk < K) {
                    const float* p = A + (size_t)gr * K;
                    v.x = p[gk];
                    v.y = (gk + 1 < K) ? p[gk + 1] : 0.f;
                    v.z = (gk + 2 < K) ? p[gk + 2] : 0.f;
                    v.w = (gk + 3 < K) ? p[gk + 3] : 0.f;
                }
            }
            areg[q] = v;
        }
    };
    auto stsA = [&](int buf) {
#pragma unroll
        for (int q = 0; q < 2; q++) {
            int chunk = tid + q * 256;
            int r = chunk >> 3, c4 = (chunk & 7) * 4;
            uint32_t h01, l01, h23, l23;
            split2(areg[q].x, areg[q].y, h01, l01);
            split2(areg[q].z, areg[q].w, h23, l23);
            int base = (buf * TBM1 + r) * ASU + (c4 >> 1);
            *reinterpret_cast<uint2*>(&Ah[base]) = make_uint2(h01, h23);
            *reinterpret_cast<uint2*>(&Al[base]) = make_uint2(l01, l23);
        }
    };
    auto cpB = [&](int buf, int kt) {
        int k2t = kt >> 1;
#pragma unroll
        for (int q = 0; q < 4; q++) {
            int chunk = tid + q * 256;          // 1024 = 16 rows x 64 c4 (hi only)
            int r = chunk >> 6, c4 = (chunk & 63) * 4;
            int gk2 = k2t + r;
            int sz = (gk2 < K2) ? 16 : 0;
            const uint32_t* src = Bh2g + (size_t)(gk2 < K2 ? gk2 : 0) * HIDD + c4;
            uint32_t dst = sBh + (uint32_t)(((buf * 16 + r) * BSTF + c4) * 4);
            cp_async16(dst, src, sz);
        }
    };

    const int ktiles = (K + TBK - 1) / TBK;     // 16
    ldgA(0); stsA(0);
    cpB(0, 0); CP_COMMIT();

    int buf = 0;
    for (int t = 0; t < ktiles; t++) {
        if (t + 1 < ktiles) {
            ldgA((t + 1) * TBK);
            cpB(buf ^ 1, (t + 1) * TBK);
            CP_COMMIT();
            CP_WAIT1();
        } else {
            CP_WAIT0();
        }
        __syncthreads();

        const uint32_t* ab_h = Ah + buf * TBM1 * ASU;
        const uint32_t* ab_l = Al + buf * TBM1 * ASU;
        const uint32_t* bb_h = Bh + buf * 16 * BSTF;
#pragma unroll
        for (int ks = 0; ks < 2; ks++) {
            const int k2 = ks * 8;
            uint32_t ah[2][4], al[2][4];
#pragma unroll
            for (int mi = 0; mi < 2; mi++) {
                int m = wm + mi * 16;
                ah[mi][0] = ab_h[(m + g    ) * ASU + k2 + tg    ];
                ah[mi][1] = ab_h[(m + g + 8) * ASU + k2 + tg    ];
                ah[mi][2] = ab_h[(m + g    ) * ASU + k2 + 4 + tg];
                ah[mi][3] = ab_h[(m + g + 8) * ASU + k2 + 4 + tg];
                al[mi][0] = ab_l[(m + g    ) * ASU + k2 + tg    ];
                al[mi][1] = ab_l[(m + g + 8) * ASU + k2 + tg    ];
                al[mi][2] = ab_l[(m + g    ) * ASU + k2 + 4 + tg];
                al[mi][3] = ab_l[(m + g + 8) * ASU + k2 + 4 + tg];
            }
#pragma unroll
            for (int ni = 0; ni < 8; ni++) {
                int n = wn + ni * 8;
                uint32_t bh[2];
                bh[0] = bb_h[(k2 + tg    ) * BSTF + n + g];
                bh[1] = bb_h[(k2 + 4 + tg) * BSTF + n + g];
#pragma unroll
                for (int mi = 0; mi < 2; mi++) {
                    mma_f16(acc[mi][ni], ah[mi], bh);
                    mma_f16(acc[mi][ni], al[mi], bh);
                }
            }
        }
        if (t + 1 < ktiles) stsA(buf ^ 1);
        __syncthreads();
        buf ^= 1;
    }

    // ---------------- transition: stage x1 tile -> smem, prefetch W2 tile 0 ----------------
    auto loadW2 = [&](int b, int k2t) {
#pragma unroll
        for (int q = 0; q < 2; q++) {
            int chunk = tid + q * 256;          // 512 = 2 planes x 16 rows x 16 c4
            int plane = chunk >> 8;
            int cc = chunk & 255;
            int r = cc >> 4, c4 = (cc & 15) * 4;
            const uint32_t* src = (plane ? W2lg : W2hg) + (size_t)(k2t + r) * 64 + c4;
            uint32_t dst = (plane ? sW2l : sW2h) + (uint32_t)(((b * 16 + r) * W2ST + c4) * 4);
            cp_async16(dst, src, 16);
        }
    };

    loadW2(0, 0);
    CP_COMMIT();
#pragma unroll
    for (int mi = 0; mi < 2; mi++) {
#pragma unroll
        for (int ni = 0; ni < 8; ni++) {
            int c = wn + ni * 8 + 2 * tg;
            float bv0 = bias1[c], bv1 = bias1[c + 1];
            int rA = wm + mi * 16 + g;
            int rB = rA + 8;
            float v0 = fmaxf(acc[mi][ni][0] + bv0, 0.f);
            float v1 = fmaxf(acc[mi][ni][1] + bv1, 0.f);
            float v2 = fmaxf(acc[mi][ni][2] + bv0, 0.f);
            float v3 = fmaxf(acc[mi][ni][3] + bv1, 0.f);
            uint32_t h, l;
            split2(v0, v1, h, l);
            X1h[rA * X1ST + (c >> 1)] = h;
            X1l[rA * X1ST + (c >> 1)] = l;
            split2(v2, v3, h, l);
            X1h[rB * X1ST + (c >> 1)] = h;
            X1l[rB * X1ST + (c >> 1)] = l;
        }
    }

    // ---------------- phase 2: H0(64x50) = x1tile(64x256) @ W2 (3-term) ----------------
    const int wm2 = (wid & 1) * 32;
    const int wn2 = (wid >> 1) * 16;

    float acc2[2][2][4];
#pragma unroll
    for (int i = 0; i < 2; i++)
#pragma unroll
        for (int j = 0; j < 2; j++)
#pragma unroll
            for (int q = 0; q < 4; q++) acc2[i][j][q] = 0.f;

    int buf2 = 0;
    for (int t = 0; t < 8; t++) {               // 8 k2-tiles of 16 (K=256)
        if (t + 1 < 8) {
            loadW2(buf2 ^ 1, (t + 1) * 16);
            CP_COMMIT();
            CP_WAIT1();
        } else {
            CP_WAIT0();
        }
        __syncthreads();

        const uint32_t* wb_h = W2h + buf2 * 16 * W2ST;
        const uint32_t* wb_l = W2l + buf2 * 16 * W2ST;
        const int k2base = t * 16;
#pragma unroll
        for (int ks = 0; ks < 2; ks++) {
            const int k2 = ks * 8;              // local W2 row index within tile
            const int kc = k2base + k2;         // global X1 column index
            uint32_t ah[2][4], al[2][4], bh[2][2], bl[2][2];
#pragma unroll
            for (int mi = 0; mi < 2; mi++) {
                int m = wm2 + mi * 16;
                ah[mi][0] = X1h[(m + g    ) * X1ST + kc + tg    ];
                ah[mi][1] = X1h[(m + g + 8) * X1ST + kc + tg    ];
                ah[mi][2] = X1h[(m + g    ) * X1ST + kc + 4 + tg];
                ah[mi][3] = X1h[(m + g + 8) * X1ST + kc + 4 + tg];
                al[mi][0] = X1l[(m + g    ) * X1ST + kc + tg    ];
                al[mi][1] = X1l[(m + g + 8) * X1ST + kc + tg    ];
                al[mi][2] = X1l[(m + g    ) * X1ST + kc + 4 + tg];
                al[mi][3] = X1l[(m + g + 8) * X1ST + kc + 4 + tg];
            }
#pragma unroll
            for (int ni = 0; ni < 2; ni++) {
                int n = wn2 + ni * 8;
                bh[ni][0] = wb_h[(k2 + tg    ) * W2ST + n + g];
                bh[ni][1] = wb_h[(k2 + 4 + tg) * W2ST + n + g];
                bl[ni][0] = wb_l[(k2 + tg    ) * W2ST + n + g];
                bl[ni][1] = wb_l[(k2 + 4 + tg) * W2ST + n + g];
            }
#pragma unroll
            for (int mi = 0; mi < 2; mi++)
#pragma unroll
                for (int ni = 0; ni < 2; ni++) {
                    mma_f16(acc2[mi][ni], ah[mi], bh[ni]);
                    mma_f16(acc2[mi][ni], al[mi], bh[ni]);
                    mma_f16(acc2[mi][ni], ah[mi], bl[ni]);
                }
        }
        __syncthreads();
        buf2 ^= 1;
    }

    // epilogue 2: bias2, write H0 (stride HLD, cols < CDIM)
#pragma unroll
    for (int mi = 0; mi < 2; mi++) {
#pragma unroll
        for (int ni = 0; ni < 2; ni++) {
            int c = wn2 + ni * 8 + 2 * tg;
            if (c >= CDIM) continue;
            float bv0 = bias2[c];
            float bv1 = (c + 1 < CDIM) ? bias2[c + 1] : 0.f;
            int r0 = row0 + wm2 + mi * 16 + g;
            int r1 = r0 + 8;
            if (r0 < M) {
                float v0 = acc2[mi][ni][0] + bv0;
                float v1 = acc2[mi][ni][1] + bv1;
                if (c + 1 < CDIM)
                    *reinterpret_cast<float2*>(C + (size_t)r0 * HLD + c) = make_float2(v0, v1);
                else
                    C[(size_t)r0 * HLD + c] = v0;
            }
            if (r1 < M) {
                float v2 = acc2[mi][ni][2] + bv0;
                float v3 = acc2[mi][ni][3] + bv1;
                if (c + 1 < CDIM)
                    *reinterpret_cast<float2*>(C + (size_t)r1 * HLD + c) = make_float2(v2, v3);
                else
                    C[(size_t)r1 * HLD + c] = v2;
            }
        }
    }
}

// ---------------- CSR build helpers ----------------
__global__ void hist_kernel(const int* __restrict__ dst, int* __restrict__ deg, int E) {
    int i = blockIdx.x * blockDim.x + threadIdx.x;
    if (i < E) atomicAdd(&deg[dst[i]], 1);
}

__global__ void norm_kernel(const int* __restrict__ deg, float* __restrict__ nrm, int n) {
    int i = blockIdx.x * blockDim.x + threadIdx.x;
    if (i < n) nrm[i] = rsqrtf((float)deg[i]);
}

__global__ void scan_block(const int* __restrict__ deg, int* __restrict__ rowptr,
                           int* __restrict__ bsum, int n) {
    __shared__ int sh[512];
    int tid = threadIdx.x;
    int gid = blockIdx.x * 512 + tid;
    int v = (gid < n) ? deg[gid] : 0;
    sh[tid] = v;
    __syncthreads();
    for (int off = 1; off < 512; off <<= 1) {
        int t = (tid >= off) ? sh[tid - off] : 0;
        __syncthreads();
        sh[tid] += t;
        __syncthreads();
    }
    if (gid < n) rowptr[gid] = sh[tid] - v;
    if (tid == 511) bsum[blockIdx.x] = sh[511];
}

__global__ void scan_sums(int* __restrict__ bsum, int nb) {
    __shared__ int sh[1024];
    int tid = threadIdx.x;
    int v = (tid < nb) ? bsum[tid] : 0;
    sh[tid] = v;
    __syncthreads();
    for (int off = 1; off < 1024; off <<= 1) {
        int t = (tid >= off) ? sh[tid - off] : 0;
        __syncthreads();
        sh[tid] += t;
        __syncthreads();
    }
    if (tid < nb) bsum[tid] = sh[tid] - v;
}

__global__ void scan_finish(int* __restrict__ rowptr, const int* __restrict__ bsum,
                            int* __restrict__ cursor, int n, int E) {
    int gid = blockIdx.x * blockDim.x + threadIdx.x;
    if (gid < n) {
        int r = rowptr[gid] + bsum[gid / 512];
        rowptr[gid] = r;
        cursor[gid] = r;
    }
    if (gid == 0) rowptr[n] = E;
}

__global__ void fill_kernel(const int* __restrict__ src, const int* __restrict__ dst,
                            int* __restrict__ cursor, int* __restrict__ col, int E) {
    int e = blockIdx.x * blockDim.x + threadIdx.x;
    if (e >= E) return;
    int pos = atomicAdd(&cursor[dst[e]], 1);
    col[pos] = src[e];
}

// ---------------- fused pull-gather hop (padded rows, float2 lanes) ----------------
__global__ void spmm_pull(const int* __restrict__ rowptr, const int* __restrict__ col,
                          const float* __restrict__ nrm,
                          const float* __restrict__ hin, float* __restrict__ hout,
                          int N) {
    int t = blockIdx.x * blockDim.x + threadIdx.x;
    int n = t >> 5;
    int lane = t & 31;
    if (n >= N) return;

    int beg = rowptr[n];
    int end = rowptr[n + 1];
    const bool act = (lane < CDIM / 2);
    const int  c2  = lane * 2;

    float ax = 0.f, ay = 0.f;
    int j = beg;
    for (; j + 3 < end; j += 4) {
        int s0 = col[j], s1 = col[j + 1], s2 = col[j + 2], s3 = col[j + 3];
        float n0 = nrm[s0], n1 = nrm[s1], n2 = nrm[s2], n3 = nrm[s3];
        if (act) {
            float2 v0 = *reinterpret_cast<const float2*>(hin + (size_t)s0 * HLD + c2);
            float2 v1 = *reinterpret_cast<const float2*>(hin + (size_t)s1 * HLD + c2);
            float2 v2 = *reinterpret_cast<const float2*>(hin + (size_t)s2 * HLD + c2);
            float2 v3 = *reinterpret_cast<const float2*>(hin + (size_t)s3 * HLD + c2);
            ax += n0 * v0.x + n1 * v1.x + n2 * v2.x + n3 * v3.x;
            ay += n0 * v0.y + n1 * v1.y + n2 * v2.y + n3 * v3.y;
        }
    }
    for (; j < end; j++) {
        int s0 = col[j];
        float n0 = nrm[s0];
        if (act) {
            float2 v0 = *reinterpret_cast<const float2*>(hin + (size_t)s0 * HLD + c2);
            ax += n0 * v0.x;
            ay += n0 * v0.y;
        }
    }
    if (act) {
        float nd = nrm[n];
        *reinterpret_cast<float2*>(hout + (size_t)n * HLD + c2) = make_float2(nd * ax, nd * ay);
    }
}

// ---------------- final sigmoid-gated combine ----------------
__global__ void final_kernel(const float* __restrict__ H, const float* __restrict__ s,
                             float* __restrict__ out, int N) {
    int t = blockIdx.x * blockDim.x + threadIdx.x;
    int n = t >> 5;
    int lane = t & 31;
    if (n >= N) return;

    const bool act = (lane < CDIM / 2);
    const int  c2  = lane * 2;
    float sx = act ? s[c2] : 0.f;
    float sy = act ? s[c2 + 1] : 0.f;

    float ax = 0.f, ay = 0.f;
    size_t plane = (size_t)N * HLD;
    const float* base = H + (size_t)n * HLD;

#pragma unroll
    for (int k = 0; k <= KHOP; k++) {
        float2 h = act ? *reinterpret_cast<const float2*>(base + (size_t)k * plane + c2)
                       : make_float2(0.f, 0.f);
        float dot = h.x * sx + h.y * sy;
#pragma unroll
        for (int off = 16; off; off >>= 1)
            dot += __shfl_xor_sync(0xffffffffu, dot, off);
        float S = 1.f / (1.f + __expf(-dot));
        ax += S * h.x;
        ay += S * h.y;
    }
    if (act)
        *reinterpret_cast<float2*>(out + (size_t)n * CDIM + c2) = make_float2(ax, ay);
}

// ---------------- launch ----------------
extern "C" void kernel_launch(void* const* d_in, const int* in_sizes, int n_in,
                              void* d_out, int out_size) {
    const float* feats = (const float*)d_in[0];
    const float* W1    = (const float*)d_in[1];
    const float* b1    = (const float*)d_in[2];
    const float* W2    = (const float*)d_in[3];
    const float* b2    = (const float*)d_in[4];
    const float* svec  = (const float*)d_in[5];
    const int*   src   = (const int*)d_in[6];
    const int*   dst   = (const int*)d_in[7];
    float* out = (float*)d_out;

    const int N = in_sizes[0] / INDIM;
    const int E = in_sizes[6];

    void *pv;
    cudaGetSymbolAddress(&pv, g_H);      float*    H      = (float*)pv;
    cudaGetSymbolAddress(&pv, g_norm);   float*    nrm    = (float*)pv;
    cudaGetSymbolAddress(&pv, g_deg);    int*      deg    = (int*)pv;
    cudaGetSymbolAddress(&pv, g_rowptr); int*      rowptr = (int*)pv;
    cudaGetSymbolAddress(&pv, g_cursor); int*      cursor = (int*)pv;
    cudaGetSymbolAddress(&pv, g_bsum);   int*      bsum   = (int*)pv;
    cudaGetSymbolAddress(&pv, g_col);    int*      col    = (int*)pv;
    cudaGetSymbolAddress(&pv, g_w1h);    uint32_t* w1h    = (uint32_t*)pv;
    cudaGetSymbolAddress(&pv, g_w1l);    uint32_t* w1l    = (uint32_t*)pv;
    cudaGetSymbolAddress(&pv, g_w2h);    uint32_t* w2h    = (uint32_t*)pv;
    cudaGetSymbolAddress(&pv, g_w2l);    uint32_t* w2l    = (uint32_t*)pv;

    const size_t plane = (size_t)N * HLD;
    const int nb = (N + 511) / 512;

    // smem: max(phase1 54272 B, phase2 (16896 + 4608) * 4 = 86016 B) -> 2 CTA/SM
    const int smem_p1 = (2 * TBM1 * ASU * 2 + 2 * 16 * BSTF) * 4;
    const int smem_p2 = (TBM1 * X1ST * 2 + 2 * 16 * W2ST * 2) * 4;
    const int smemF = smem_p1 > smem_p2 ? smem_p1 : smem_p2;
    cudaFuncSetAttribute(mlp_fused, cudaFuncAttributeMaxDynamicSharedMemorySize, smemF);

    // 0) pre-split weights into packed fp16 k-pair planes
    decomp_pair<<<((INDIM / 2) * HIDD + 255) / 256, 256>>>(W1, w1h, w1l, INDIM, HIDD, HIDD);
    decomp_pair<<<((HIDD / 2) * 64 + 255) / 256, 256>>>(W2, w2h, w2l, HIDD, CDIM, 64);

    // 1+2) fused MLP -> H0
    {
        dim3 grid((N + TBM1 - 1) / TBM1);
        mlp_fused<<<grid, 256, smemF>>>(feats, w1h, b1, w2h, w2l, b2, H, N, INDIM);
    }
    // 3) CSR build
    cudaMemsetAsync(deg, 0, (size_t)N * sizeof(int));
    hist_kernel<<<(E + 255) / 256, 256>>>(dst, deg, E);
    norm_kernel<<<(N + 255) / 256, 256>>>(deg, nrm, N);
    scan_block<<<nb, 512>>>(deg, rowptr, bsum, N);
    scan_sums<<<1, 1024>>>(bsum, nb);
    scan_finish<<<(N + 255) / 256, 256>>>(rowptr, bsum, cursor, N, E);
    fill_kernel<<<(E + 255) / 256, 256>>>(src, dst, cursor, col, E);

    // 4) K propagation hops
    for (int k = 1; k <= KHOP; k++) {
        const float* hin = H + (size_t)(k - 1) * plane;
        float* hout      = H + (size_t)k * plane;
        spmm_pull<<<(N * 32 + 255) / 256, 256>>>(rowptr, col, nrm, hin, hout, N);
    }

    // 5) sigmoid-gated combine
    final_kernel<<<(N * 32 + 255) / 256, 256>>>(H, svec, out, N);
}

// round 12
// speedup vs baseline: 2.1265x; 1.2124x over previous
#include <cuda_runtime.h>
#include <cuda_fp16.h>
#include <cstdint>

#define NMAX   100000
#define EMAX   1600000
#define CDIM   50
#define HLD    64            // padded H row stride (floats)
#define HIDD   256
#define INDIM  500
#define KHOP   10

// ---------------- static scratch (no allocations allowed) ----------------
static __device__ __align__(16) float    g_H [(size_t)(KHOP + 1) * NMAX * HLD];
static __device__ float    g_norm[NMAX];    // deg^-1/2
static __device__ float    g_nrm2[NMAX];    // deg^-1
static __device__ float    g_sdeg[NMAX];    // deg^+1/2
static __device__ int      g_deg   [NMAX];
static __device__ int      g_rowptr[NMAX + 1];
static __device__ int      g_cursor[NMAX];
static __device__ int      g_bsum  [1024];
static __device__ int      g_col   [EMAX];
static __device__ __align__(16) uint32_t g_w1h[(INDIM / 2) * HIDD];  // W1 k-pair hi plane
static __device__ __align__(16) uint32_t g_w2h[(HIDD / 2) * 64];     // W2 padded ldp=64
static __device__ __align__(16) uint32_t g_w2l[(HIDD / 2) * 64];

// ================= fp16 split helpers =================
__device__ __forceinline__ void split2(float x, float y, uint32_t& h2u, uint32_t& l2u) {
    __half2 h = __floats2half2_rn(x, y);
    float2 hf = __half22float2(h);
    __half2 l = __floats2half2_rn(x - hf.x, y - hf.y);
    h2u = *reinterpret_cast<uint32_t*>(&h);
    l2u = *reinterpret_cast<uint32_t*>(&l);
}

__device__ __forceinline__ uint32_t pack_h2(float x, float y) {
    __half2 h = __floats2half2_rn(x, y);
    return *reinterpret_cast<uint32_t*>(&h);
}

__device__ __forceinline__ void mma_f16(float* c, const uint32_t* a, const uint32_t* b) {
    asm volatile(
        "mma.sync.aligned.m16n8k16.row.col.f32.f16.f16.f32 "
        "{%0,%1,%2,%3}, {%4,%5,%6,%7}, {%8,%9}, {%0,%1,%2,%3};"
        : "+f"(c[0]), "+f"(c[1]), "+f"(c[2]), "+f"(c[3])
        : "r"(a[0]), "r"(a[1]), "r"(a[2]), "r"(a[3]), "r"(b[0]), "r"(b[1]));
}

__device__ __forceinline__ void cp_async16(uint32_t dst, const void* src, int sz) {
    asm volatile("cp.async.ca.shared.global [%0], [%1], 16, %2;"
                 :: "r"(dst), "l"(src), "r"(sz));
}
#define CP_COMMIT() asm volatile("cp.async.commit_group;")
#define CP_WAIT1()  asm volatile("cp.async.wait_group 1;")
#define CP_WAIT0()  asm volatile("cp.async.wait_group 0;")

// W [K][N] fp32 -> packed k-pair fp16 hi plane [K/2][ldp] (cols zero-padded)
__global__ void decomp_hi(const float* __restrict__ W,
                          uint32_t* __restrict__ Wh2, int K, int N, int ldp) {
    int i = blockIdx.x * blockDim.x + threadIdx.x;
    if (i >= (K / 2) * ldp) return;
    int k2 = i / ldp, c = i % ldp;
    float x = (c < N) ? W[(size_t)(2 * k2) * N + c] : 0.f;
    float y = (c < N) ? W[(size_t)(2 * k2 + 1) * N + c] : 0.f;
    Wh2[i] = pack_h2(x, y);
}

// W [K][N] fp32 -> packed hi+lo planes (for W2, kept 2-plane)
__global__ void decomp_pair(const float* __restrict__ W,
                            uint32_t* __restrict__ Wh2, uint32_t* __restrict__ Wl2,
                            int K, int N, int ldp) {
    int i = blockIdx.x * blockDim.x + threadIdx.x;
    if (i >= (K / 2) * ldp) return;
    int k2 = i / ldp, c = i % ldp;
    float x = (c < N) ? W[(size_t)(2 * k2) * N + c] : 0.f;
    float y = (c < N) ? W[(size_t)(2 * k2 + 1) * N + c] : 0.f;
    uint32_t h, l; split2(x, y, h, l);
    Wh2[i] = h; Wl2[i] = l;
}

// ================= fused MLP: t0 = nrm * (relu(feats@W1+b1) @ W2 + b2) =================
// Phase 1: single-term fp16 (Ah·Bh). Phase 2: 3-term via smem x1.
#define TBM1 64
#define TBK  32            // k per tile (k2 = 16)
#define ASU  20            // A smem u32 row stride
#define BSTF 264           // phase-1 B smem row stride (256 + 8)
#define X1ST 132           // x1 smem tile row stride (128 + 4)
#define W2ST 72            // phase-2 W2 smem row stride (64 + 8)

__global__ __launch_bounds__(256, 2)
void mlp_fused(const float* __restrict__ A,
               const uint32_t* __restrict__ Bh2g,
               const float* __restrict__ bias1,
               const uint32_t* __restrict__ W2hg, const uint32_t* __restrict__ W2lg,
               const float* __restrict__ bias2,
               const float* __restrict__ nrm,
               float* __restrict__ C, int M, int K) {
    extern __shared__ uint8_t dyn[];
    // phase-1 layout (hi planes only)
    uint32_t* Ah = (uint32_t*)dyn;                 // [2][64][ASU]
    uint32_t* Bh = Ah + 2 * TBM1 * ASU;            // [2][16][BSTF]
    // phase-2 layout (aliases region; phase-1 data dead by then)
    uint32_t* X1h = (uint32_t*)dyn;                // [64][X1ST]
    uint32_t* X1l = X1h + TBM1 * X1ST;
    uint32_t* W2h = X1l + TBM1 * X1ST;             // [2][16][W2ST]
    uint32_t* W2l = W2h + 2 * 16 * W2ST;           // [2][16][W2ST]

    const uint32_t sBh  = (uint32_t)__cvta_generic_to_shared(Bh);
    const uint32_t sW2h = (uint32_t)__cvta_generic_to_shared(W2h);
    const uint32_t sW2l = (uint32_t)__cvta_generic_to_shared(W2l);

    const int tid  = threadIdx.x;
    const int lane = tid & 31;
    const int wid  = tid >> 5;
    const int g    = lane >> 2;
    const int tg   = lane & 3;
    const int row0 = blockIdx.x * TBM1;
    const int K2   = K / 2;                        // 250

    // ---------------- phase 1: warp tile 32x64 over 256 cols ----------------
    const int wm = (wid & 1) * 32;
    const int wn = (wid >> 1) * 64;

    float acc[2][8][4];
#pragma unroll
    for (int i = 0; i < 2; i++)
#pragma unroll
        for (int j = 0; j < 8; j++)
#pragma unroll
            for (int q = 0; q < 4; q++) acc[i][j][q] = 0.f;

    float4 areg[2];
    auto ldgA = [&](int kt) {
#pragma unroll
        for (int q = 0; q < 2; q++) {
            int chunk = tid + q * 256;          // 512 = 64 rows x 8 float4
            int r = chunk >> 3, c4 = (chunk & 7) * 4;
            int gr = row0 + r, gk = kt + c4;
            float4 v = make_float4(0.f, 0.f, 0.f, 0.f);
            if (gr < M) {
                if (gk + 3 < K) {
                    v = *reinterpret_cast<const float4*>(A + (size_t)gr * K + gk);
                } else if (gk < K) {
                    const float* p = A + (size_t)gr * K;
                    v.x = p[gk];
                    v.y = (gk + 1 < K) ? p[gk + 1] : 0.f;
                    v.z = (gk + 2 < K) ? p[gk + 2] : 0.f;
                    v.w = (gk + 3 < K) ? p[gk + 3] : 0.f;
                }
            }
            areg[q] = v;
        }
    };
    auto stsA = [&](int buf) {
#pragma unroll
        for (int q = 0; q < 2; q++) {
            int chunk = tid + q * 256;
            int r = chunk >> 3, c4 = (chunk & 7) * 4;
            uint32_t h01 = pack_h2(areg[q].x, areg[q].y);
            uint32_t h23 = pack_h2(areg[q].z, areg[q].w);
            int base = (buf * TBM1 + r) * ASU + (c4 >> 1);
            *reinterpret_cast<uint2*>(&Ah[base]) = make_uint2(h01, h23);
        }
    };
    auto cpB = [&](int buf, int kt) {
        int k2t = kt >> 1;
#pragma unroll
        for (int q = 0; q < 4; q++) {
            int chunk = tid + q * 256;          // 1024 = 16 rows x 64 c4 (hi only)
            int r = chunk >> 6, c4 = (chunk & 63) * 4;
            int gk2 = k2t + r;
            int sz = (gk2 < K2) ? 16 : 0;
            const uint32_t* src = Bh2g + (size_t)(gk2 < K2 ? gk2 : 0) * HIDD + c4;
            uint32_t dst = sBh + (uint32_t)(((buf * 16 + r) * BSTF + c4) * 4);
            cp_async16(dst, src, sz);
        }
    };

    const int ktiles = (K + TBK - 1) / TBK;     // 16
    ldgA(0); stsA(0);
    cpB(0, 0); CP_COMMIT();

    int buf = 0;
    for (int t = 0; t < ktiles; t++) {
        if (t + 1 < ktiles) {
            ldgA((t + 1) * TBK);
            cpB(buf ^ 1, (t + 1) * TBK);
            CP_COMMIT();
            CP_WAIT1();
        } else {
            CP_WAIT0();
        }
        __syncthreads();

        const uint32_t* ab_h = Ah + buf * TBM1 * ASU;
        const uint32_t* bb_h = Bh + buf * 16 * BSTF;
#pragma unroll
        for (int ks = 0; ks < 2; ks++) {
            const int k2 = ks * 8;
            uint32_t ah[2][4];
#pragma unroll
            for (int mi = 0; mi < 2; mi++) {
                int m = wm + mi * 16;
                ah[mi][0] = ab_h[(m + g    ) * ASU + k2 + tg    ];
                ah[mi][1] = ab_h[(m + g + 8) * ASU + k2 + tg    ];
                ah[mi][2] = ab_h[(m + g    ) * ASU + k2 + 4 + tg];
                ah[mi][3] = ab_h[(m + g + 8) * ASU + k2 + 4 + tg];
            }
#pragma unroll
            for (int ni = 0; ni < 8; ni++) {
                int n = wn + ni * 8;
                uint32_t bh[2];
                bh[0] = bb_h[(k2 + tg    ) * BSTF + n + g];
                bh[1] = bb_h[(k2 + 4 + tg) * BSTF + n + g];
#pragma unroll
                for (int mi = 0; mi < 2; mi++)
                    mma_f16(acc[mi][ni], ah[mi], bh);
            }
        }
        if (t + 1 < ktiles) stsA(buf ^ 1);
        __syncthreads();
        buf ^= 1;
    }

    // ---------------- transition: stage x1 tile -> smem (split), prefetch W2 tile 0 ----------------
    auto loadW2 = [&](int b, int k2t) {
#pragma unroll
        for (int q = 0; q < 2; q++) {
            int chunk = tid + q * 256;          // 512 = 2 planes x 16 rows x 16 c4
            int plane = chunk >> 8;
            int cc = chunk & 255;
            int r = cc >> 4, c4 = (cc & 15) * 4;
            const uint32_t* src = (plane ? W2lg : W2hg) + (size_t)(k2t + r) * 64 + c4;
            uint32_t dst = (plane ? sW2l : sW2h) + (uint32_t)(((b * 16 + r) * W2ST + c4) * 4);
            cp_async16(dst, src, 16);
        }
    };

    loadW2(0, 0);
    CP_COMMIT();
#pragma unroll
    for (int mi = 0; mi < 2; mi++) {
#pragma unroll
        for (int ni = 0; ni < 8; ni++) {
            int c = wn + ni * 8 + 2 * tg;
            float bv0 = bias1[c], bv1 = bias1[c + 1];
            int rA = wm + mi * 16 + g;
            int rB = rA + 8;
            float v0 = fmaxf(acc[mi][ni][0] + bv0, 0.f);
            float v1 = fmaxf(acc[mi][ni][1] + bv1, 0.f);
            float v2 = fmaxf(acc[mi][ni][2] + bv0, 0.f);
            float v3 = fmaxf(acc[mi][ni][3] + bv1, 0.f);
            uint32_t h, l;
            split2(v0, v1, h, l);
            X1h[rA * X1ST + (c >> 1)] = h;
            X1l[rA * X1ST + (c >> 1)] = l;
            split2(v2, v3, h, l);
            X1h[rB * X1ST + (c >> 1)] = h;
            X1l[rB * X1ST + (c >> 1)] = l;
        }
    }

    // ---------------- phase 2: t0(64x50) = (x1tile @ W2 + b2) * nrm ----------------
    const int wm2 = (wid & 1) * 32;
    const int wn2 = (wid >> 1) * 16;

    float acc2[2][2][4];
#pragma unroll
    for (int i = 0; i < 2; i++)
#pragma unroll
        for (int j = 0; j < 2; j++)
#pragma unroll
            for (int q = 0; q < 4; q++) acc2[i][j][q] = 0.f;

    int buf2 = 0;
    for (int t = 0; t < 8; t++) {               // 8 k2-tiles of 16 (K=256)
        if (t + 1 < 8) {
            loadW2(buf2 ^ 1, (t + 1) * 16);
            CP_COMMIT();
            CP_WAIT1();
        } else {
            CP_WAIT0();
        }
        __syncthreads();

        const uint32_t* wb_h = W2h + buf2 * 16 * W2ST;
        const uint32_t* wb_l = W2l + buf2 * 16 * W2ST;
        const int k2base = t * 16;
#pragma unroll
        for (int ks = 0; ks < 2; ks++) {
            const int k2 = ks * 8;              // local W2 row index within tile
            const int kc = k2base + k2;         // global X1 column index
            uint32_t ah[2][4], al[2][4], bh[2][2], bl[2][2];
#pragma unroll
            for (int mi = 0; mi < 2; mi++) {
                int m = wm2 + mi * 16;
                ah[mi][0] = X1h[(m + g    ) * X1ST + kc + tg    ];
                ah[mi][1] = X1h[(m + g + 8) * X1ST + kc + tg    ];
                ah[mi][2] = X1h[(m + g    ) * X1ST + kc + 4 + tg];
                ah[mi][3] = X1h[(m + g + 8) * X1ST + kc + 4 + tg];
                al[mi][0] = X1l[(m + g    ) * X1ST + kc + tg    ];
                al[mi][1] = X1l[(m + g + 8) * X1ST + kc + tg    ];
                al[mi][2] = X1l[(m + g    ) * X1ST + kc + 4 + tg];
                al[mi][3] = X1l[(m + g + 8) * X1ST + kc + 4 + tg];
            }
#pragma unroll
            for (int ni = 0; ni < 2; ni++) {
                int n = wn2 + ni * 8;
                bh[ni][0] = wb_h[(k2 + tg    ) * W2ST + n + g];
                bh[ni][1] = wb_h[(k2 + 4 + tg) * W2ST + n + g];
                bl[ni][0] = wb_l[(k2 + tg    ) * W2ST + n + g];
                bl[ni][1] = wb_l[(k2 + 4 + tg) * W2ST + n + g];
            }
#pragma unroll
            for (int mi = 0; mi < 2; mi++)
#pragma unroll
                for (int ni = 0; ni < 2; ni++) {
                    mma_f16(acc2[mi][ni], ah[mi], bh[ni]);
                    mma_f16(acc2[mi][ni], al[mi], bh[ni]);
                    mma_f16(acc2[mi][ni], ah[mi], bl[ni]);
                }
        }
        __syncthreads();
        buf2 ^= 1;
    }

    // epilogue 2: bias2, scale by nrm, write t0 (stride HLD, cols < CDIM)
#pragma unroll
    for (int mi = 0; mi < 2; mi++) {
#pragma unroll
        for (int ni = 0; ni < 2; ni++) {
            int c = wn2 + ni * 8 + 2 * tg;
            if (c >= CDIM) continue;
            float bv0 = bias2[c];
            float bv1 = (c + 1 < CDIM) ? bias2[c + 1] : 0.f;
            int r0 = row0 + wm2 + mi * 16 + g;
            int r1 = r0 + 8;
            if (r0 < M) {
                float nd = nrm[r0];
                float v0 = (acc2[mi][ni][0] + bv0) * nd;
                float v1 = (acc2[mi][ni][1] + bv1) * nd;
                if (c + 1 < CDIM)
                    *reinterpret_cast<float2*>(C + (size_t)r0 * HLD + c) = make_float2(v0, v1);
                else
                    C[(size_t)r0 * HLD + c] = v0;
            }
            if (r1 < M) {
                float nd = nrm[r1];
                float v2 = (acc2[mi][ni][2] + bv0) * nd;
                float v3 = (acc2[mi][ni][3] + bv1) * nd;
                if (c + 1 < CDIM)
                    *reinterpret_cast<float2*>(C + (size_t)r1 * HLD + c) = make_float2(v2, v3);
                else
                    C[(size_t)r1 * HLD + c] = v2;
            }
        }
    }
}

// ---------------- CSR build helpers ----------------
__global__ void hist_kernel(const int* __restrict__ dst, int* __restrict__ deg, int E) {
    int i = blockIdx.x * blockDim.x + threadIdx.x;
    if (i < E) atomicAdd(&deg[dst[i]], 1);
}

__global__ void norm_kernel(const int* __restrict__ deg, float* __restrict__ nrm,
                            float* __restrict__ nrm2, float* __restrict__ sdeg, int n) {
    int i = blockIdx.x * blockDim.x + threadIdx.x;
    if (i < n) {
        float d = (float)deg[i];
        nrm[i]  = rsqrtf(d);
        nrm2[i] = 1.0f / d;
        sdeg[i] = sqrtf(d);
    }
}

__global__ void scan_block(const int* __restrict__ deg, int* __restrict__ rowptr,
                           int* __restrict__ bsum, int n) {
    __shared__ int sh[512];
    int tid = threadIdx.x;
    int gid = blockIdx.x * 512 + tid;
    int v = (gid < n) ? deg[gid] : 0;
    sh[tid] = v;
    __syncthreads();
    for (int off = 1; off < 512; off <<= 1) {
        int t = (tid >= off) ? sh[tid - off] : 0;
        __syncthreads();
        sh[tid] += t;
        __syncthreads();
    }
    if (gid < n) rowptr[gid] = sh[tid] - v;
    if (tid == 511) bsum[blockIdx.x] = sh[511];
}

__global__ void scan_sums(int* __restrict__ bsum, int nb) {
    __shared__ int sh[1024];
    int tid = threadIdx.x;
    int v = (tid < nb) ? bsum[tid] : 0;
    sh[tid] = v;
    __syncthreads();
    for (int off = 1; off < 1024; off <<= 1) {
        int t = (tid >= off) ? sh[tid - off] : 0;
        __syncthreads();
        sh[tid] += t;
        __syncthreads();
    }
    if (tid < nb) bsum[tid] = sh[tid] - v;
}

__global__ void scan_finish(int* __restrict__ rowptr, const int* __restrict__ bsum,
                            int* __restrict__ cursor, int n, int E) {
    int gid = blockIdx.x * blockDim.x + threadIdx.x;
    if (gid < n) {
        int r = rowptr[gid] + bsum[gid / 512];
        rowptr[gid] = r;
        cursor[gid] = r;
    }
    if (gid == 0) rowptr[n] = E;
}

__global__ void fill_kernel(const int* __restrict__ src, const int* __restrict__ dst,
                            int* __restrict__ cursor, int* __restrict__ col, int E) {
    int e = blockIdx.x * blockDim.x + threadIdx.x;
    if (e >= E) return;
    int pos = atomicAdd(&cursor[dst[e]], 1);
    col[pos] = src[e];
}

// ---------------- pull-gather hop on pre-scaled planes ----------------
// t_out[d] = nrm2[d] * sum_{s in N(d)} t_in[s]   (pure adds, no per-edge nrm)
__global__ void spmm_pull(const int* __restrict__ rowptr, const int* __restrict__ col,
                          const float* __restrict__ nrm2,
                          const float* __restrict__ hin, float* __restrict__ hout,
                          int N) {
    int t = blockIdx.x * blockDim.x + threadIdx.x;
    int n = t >> 5;
    int lane = t & 31;
    if (n >= N) return;

    int beg = rowptr[n];
    int end = rowptr[n + 1];
    const bool act = (lane < CDIM / 2);
    const int  c2  = lane * 2;

    float ax = 0.f, ay = 0.f;
    int j = beg;
    for (; j + 3 < end; j += 4) {
        int s0 = col[j], s1 = col[j + 1], s2 = col[j + 2], s3 = col[j + 3];
        if (act) {
            float2 v0 = *reinterpret_cast<const float2*>(hin + (size_t)s0 * HLD + c2);
            float2 v1 = *reinterpret_cast<const float2*>(hin + (size_t)s1 * HLD + c2);
            float2 v2 = *reinterpret_cast<const float2*>(hin + (size_t)s2 * HLD + c2);
            float2 v3 = *reinterpret_cast<const float2*>(hin + (size_t)s3 * HLD + c2);
            ax += (v0.x + v1.x) + (v2.x + v3.x);
            ay += (v0.y + v1.y) + (v2.y + v3.y);
        }
    }
    for (; j < end; j++) {
        int s0 = col[j];
        if (act) {
            float2 v0 = *reinterpret_cast<const float2*>(hin + (size_t)s0 * HLD + c2);
            ax += v0.x;
            ay += v0.y;
        }
    }
    if (act) {
        float w = nrm2[n];
        *reinterpret_cast<float2*>(hout + (size_t)n * HLD + c2) = make_float2(w * ax, w * ay);
    }
}

// ---------------- final sigmoid-gated combine (unscale by sqrt(deg)) ----------------
__global__ void final_kernel(const float* __restrict__ H, const float* __restrict__ s,
                             const float* __restrict__ sdeg,
                             float* __restrict__ out, int N) {
    int t = blockIdx.x * blockDim.x + threadIdx.x;
    int n = t >> 5;
    int lane = t & 31;
    if (n >= N) return;

    const bool act = (lane < CDIM / 2);
    const int  c2  = lane * 2;
    float sx = act ? s[c2] : 0.f;
    float sy = act ? s[c2 + 1] : 0.f;
    float inv = sdeg[n];                 // h_k = t_k * sqrt(deg)

    float ax = 0.f, ay = 0.f;
    size_t plane = (size_t)N * HLD;
    const float* base = H + (size_t)n * HLD;

#pragma unroll
    for (int k = 0; k <= KHOP; k++) {
        float2 tv = act ? *reinterpret_cast<const float2*>(base + (size_t)k * plane + c2)
                        : make_float2(0.f, 0.f);
        float hx = tv.x * inv, hy = tv.y * inv;
        float dot = hx * sx + hy * sy;
#pragma unroll
        for (int off = 16; off; off >>= 1)
            dot += __shfl_xor_sync(0xffffffffu, dot, off);
        float S = 1.f / (1.f + __expf(-dot));
        ax += S * hx;
        ay += S * hy;
    }
    if (act)
        *reinterpret_cast<float2*>(out + (size_t)n * CDIM + c2) = make_float2(ax, ay);
}

// ---------------- launch ----------------
extern "C" void kernel_launch(void* const* d_in, const int* in_sizes, int n_in,
                              void* d_out, int out_size) {
    const float* feats = (const float*)d_in[0];
    const float* W1    = (const float*)d_in[1];
    const float* b1    = (const float*)d_in[2];
    const float* W2    = (const float*)d_in[3];
    const float* b2    = (const float*)d_in[4];
    const float* svec  = (const float*)d_in[5];
    const int*   src   = (const int*)d_in[6];
    const int*   dst   = (const int*)d_in[7];
    float* out = (float*)d_out;

    const int N = in_sizes[0] / INDIM;
    const int E = in_sizes[6];

    void *pv;
    cudaGetSymbolAddress(&pv, g_H);      float*    H      = (float*)pv;
    cudaGetSymbolAddress(&pv, g_norm);   float*    nrm    = (float*)pv;
    cudaGetSymbolAddress(&pv, g_nrm2);   float*    nrm2   = (float*)pv;
    cudaGetSymbolAddress(&pv, g_sdeg);   float*    sdeg   = (float*)pv;
    cudaGetSymbolAddress(&pv, g_deg);    int*      deg    = (int*)pv;
    cudaGetSymbolAddress(&pv, g_rowptr); int*      rowptr = (int*)pv;
    cudaGetSymbolAddress(&pv, g_cursor); int*      cursor = (int*)pv;
    cudaGetSymbolAddress(&pv, g_bsum);   int*      bsum   = (int*)pv;
    cudaGetSymbolAddress(&pv, g_col);    int*      col    = (int*)pv;
    cudaGetSymbolAddress(&pv, g_w1h);    uint32_t* w1h    = (uint32_t*)pv;
    cudaGetSymbolAddress(&pv, g_w2h);    uint32_t* w2h    = (uint32_t*)pv;
    cudaGetSymbolAddress(&pv, g_w2l);    uint32_t* w2l    = (uint32_t*)pv;

    const size_t plane = (size_t)N * HLD;
    const int nb = (N + 511) / 512;

    // smem: max(phase1 44032 B, phase2 86016 B) -> 2 CTA/SM
    const int smem_p1 = (2 * TBM1 * ASU + 2 * 16 * BSTF) * 4;
    const int smem_p2 = (TBM1 * X1ST * 2 + 2 * 16 * W2ST * 2) * 4;
    const int smemF = smem_p1 > smem_p2 ? smem_p1 : smem_p2;
    cudaFuncSetAttribute(mlp_fused, cudaFuncAttributeMaxDynamicSharedMemorySize, smemF);

    // 0) pre-split weights
    decomp_hi<<<((INDIM / 2) * HIDD + 255) / 256, 256>>>(W1, w1h, INDIM, HIDD, HIDD);
    decomp_pair<<<((HIDD / 2) * 64 + 255) / 256, 256>>>(W2, w2h, w2l, HIDD, CDIM, 64);

    // 1) CSR build first (mlp epilogue needs nrm)
    cudaMemsetAsync(deg, 0, (size_t)N * sizeof(int));
    hist_kernel<<<(E + 255) / 256, 256>>>(dst, deg, E);
    norm_kernel<<<(N + 255) / 256, 256>>>(deg, nrm, nrm2, sdeg, N);
    scan_block<<<nb, 512>>>(deg, rowptr, bsum, N);
    scan_sums<<<1, 1024>>>(bsum, nb);
    scan_finish<<<(N + 255) / 256, 256>>>(rowptr, bsum, cursor, N, E);
    fill_kernel<<<(E + 255) / 256, 256>>>(src, dst, cursor, col, E);

    // 2) fused MLP -> t0 = nrm * H0
    {
        dim3 grid((N + TBM1 - 1) / TBM1);
        mlp_fused<<<grid, 256, smemF>>>(feats, w1h, b1, w2h, w2l, b2, nrm, H, N, INDIM);
    }

    // 3) K propagation hops on pre-scaled planes
    for (int k = 1; k <= KHOP; k++) {
        const float* hin = H + (size_t)(k - 1) * plane;
        float* hout      = H + (size_t)k * plane;
        spmm_pull<<<(N * 32 + 255) / 256, 256>>>(rowptr, col, nrm2, hin, hout, N);
    }

    // 4) sigmoid-gated combine (unscales by sqrt(deg))
    final_kernel<<<(N * 32 + 255) / 256, 256>>>(H, svec, sdeg, out, N);
}